// round 6
// baseline (speedup 1.0000x reference)
#include <cuda_runtime.h>
#include <cuda_bf16.h>
#include <cstdint>
#include <cstddef>

#define Bsz   4
#define Tsz   2048
#define Csz   1024
#define Hn    16
#define Dh    64
#define Mrows (Bsz * Tsz)   // 8192

// Scratch (static __device__ arrays — allocation-guard safe)
__device__ float g_qkv [(size_t)Mrows * 3 * Csz];   // [8192, 3072] (q,k thirds used)
__device__ float g_vT  [(size_t)Bsz * Hn * Dh * Tsz]; // [64 bh][64 d][2048 t]
__device__ float g_y   [(size_t)Mrows * Csz];       // [8192, 1024]  (tf32-rounded)
__device__ float g_xc  [(size_t)Mrows * Csz];       // x, tf32-rounded
__device__ float g_wqkvT[(size_t)3 * Csz * Csz];    // [3072, 1024]  (tf32-rounded)
__device__ float g_wpT [(size_t)Csz * Csz];         // [1024, 1024]  (tf32-rounded)

// ---------------------------------------------------------------------------
// Helpers (non-'a' PTX only: cp.async + mma.sync, sm_80 baseline)
// ---------------------------------------------------------------------------
__device__ __forceinline__ uint32_t smem_to_u32(const void* p) {
    uint32_t a;
    asm("{ .reg .u64 t; cvta.to.shared.u64 t, %1; cvt.u32.u64 %0, t; }"
        : "=r"(a) : "l"(p));
    return a;
}
__device__ __forceinline__ float to_tf32(float x) {
    uint32_t r;
    asm("cvt.rna.tf32.f32 %0, %1;" : "=r"(r) : "f"(x));
    return __uint_as_float(r);
}

#define CP_ASYNC16(dst, src) \
    asm volatile("cp.async.cg.shared.global [%0], [%1], 16;" :: "r"(dst), "l"(src) : "memory")
#define CP_COMMIT() asm volatile("cp.async.commit_group;" ::: "memory")
#define CP_WAIT(n)  asm volatile("cp.async.wait_group %0;" :: "n"(n) : "memory")

// D += A*B, m16n8k8 tf32 (A row-major, B col-major i.e. [n][k])
#define MMA_TF32(d, a, b) \
    asm volatile("mma.sync.aligned.m16n8k8.row.col.f32.tf32.tf32.f32 " \
        "{%0,%1,%2,%3}, {%4,%5,%6,%7}, {%8,%9}, {%0,%1,%2,%3};" \
        : "+f"((d)[0]), "+f"((d)[1]), "+f"((d)[2]), "+f"((d)[3]) \
        : "r"((a)[0]), "r"((a)[1]), "r"((a)[2]), "r"((a)[3]), \
          "r"((b)[0]), "r"((b)[1]))

// ---------------------------------------------------------------------------
// mma.sync tf32 GEMM: C[M,N] = A[M,1024] @ Bt[N,1024]^T + bias
// 128x128 tile, BK=32, 3-stage cp.async, 256 threads, warp tile 64x32.
// Explicit double-buffered fragments (prefetch ks+1 during ks MMAs).
// If vT != nullptr, tiles with col0 >= 2048 scatter to vT[bh][d][t].
// ---------------------------------------------------------------------------
#define KCHUNKS 32
#define STAGE_F 8192
#define GEMM_SMEM (3 * STAGE_F * 4)

__global__ __launch_bounds__(256) void gemm_mma_kernel(
    const float* __restrict__ A,
    const float* __restrict__ Bt,
    const float* __restrict__ bias,
    float* __restrict__ C,
    int Ntot,
    float* __restrict__ vT,
    int roundC)
{
    extern __shared__ float sm[];
    uint32_t smemB = smem_to_u32(sm);

    int tid  = threadIdx.x;
    int lane = tid & 31;
    int warp = tid >> 5;
    int wm = warp >> 2;
    int wn = warp & 3;
    int tg = lane >> 2;
    int ti = lane & 3;
    int row0 = blockIdx.y * 128;
    int col0 = blockIdx.x * 128;

    // cp.async mapping: j advances rows by 32 (mod-8 invariant -> swizzle fixed)
    int lr   = tid >> 3;                    // 0..31
    int lc4  = (tid & 7) * 4;               // float col 0..28
    int lswB = (lc4 ^ ((lr & 7) * 4)) * 4;  // swizzled byte offset in row
    const float* gA = A  + (size_t)(row0 + lr) * 1024 + lc4;
    const float* gB = Bt + (size_t)(col0 + lr) * 1024 + lc4;

    // fragment bases (float offsets; rows stride 32 floats)
    int fa = (wm * 64 + tg) * 32;
    int fb = (wn * 32 + tg) * 32;
    int kswz = tg * 4;

    float acc[4][4][4];
    #pragma unroll
    for (int i = 0; i < 4; i++)
        #pragma unroll
        for (int j = 0; j < 4; j++)
            #pragma unroll
            for (int q = 0; q < 4; q++) acc[i][j][q] = 0.f;

    auto load_stage = [&](int chunk) {
        if (chunk < KCHUNKS) {
            int s = chunk % 3;
            uint32_t base = smemB + (uint32_t)s * (STAGE_F * 4);
            const float* a = gA + chunk * 32;
            const float* b = gB + chunk * 32;
            #pragma unroll
            for (int j = 0; j < 4; j++) {
                uint32_t off = (uint32_t)((lr + 32 * j) * 128 + lswB);
                CP_ASYNC16(base + off, a + (size_t)j * 32 * 1024);
                CP_ASYNC16(base + 16384 + off, b + (size_t)j * 32 * 1024);
            }
        }
        CP_COMMIT();
    };

    load_stage(0);
    load_stage(1);
    load_stage(2);

    uint32_t af[2][4][4], bf[2][4][2];

    #pragma unroll 1
    for (int c = 0; c < KCHUNKS; ++c) {
        CP_WAIT(2);
        __syncthreads();

        const float* As = sm + (c % 3) * STAGE_F;
        const float* Bs = As + 4096;

        // prefetch ks=0 fragments
        {
            int c0 = ti ^ kswz, c1 = (ti + 4) ^ kswz;
            #pragma unroll
            for (int i = 0; i < 4; i++) {
                af[0][i][0] = __float_as_uint(As[fa + i * 512 + c0]);
                af[0][i][1] = __float_as_uint(As[fa + i * 512 + 256 + c0]);
                af[0][i][2] = __float_as_uint(As[fa + i * 512 + c1]);
                af[0][i][3] = __float_as_uint(As[fa + i * 512 + 256 + c1]);
            }
            #pragma unroll
            for (int j = 0; j < 4; j++) {
                bf[0][j][0] = __float_as_uint(Bs[fb + j * 256 + c0]);
                bf[0][j][1] = __float_as_uint(Bs[fb + j * 256 + c1]);
            }
        }

        #pragma unroll
        for (int ks = 0; ks < 4; ks++) {
            int cur = ks & 1, nxt = cur ^ 1;
            if (ks < 3) {
                int k0 = (ks + 1) * 8 + ti;
                int c0 = k0 ^ kswz, c1 = (k0 + 4) ^ kswz;
                #pragma unroll
                for (int i = 0; i < 4; i++) {
                    af[nxt][i][0] = __float_as_uint(As[fa + i * 512 + c0]);
                    af[nxt][i][1] = __float_as_uint(As[fa + i * 512 + 256 + c0]);
                    af[nxt][i][2] = __float_as_uint(As[fa + i * 512 + c1]);
                    af[nxt][i][3] = __float_as_uint(As[fa + i * 512 + 256 + c1]);
                }
                #pragma unroll
                for (int j = 0; j < 4; j++) {
                    bf[nxt][j][0] = __float_as_uint(Bs[fb + j * 256 + c0]);
                    bf[nxt][j][1] = __float_as_uint(Bs[fb + j * 256 + c1]);
                }
            }
            #pragma unroll
            for (int i = 0; i < 4; i++)
                #pragma unroll
                for (int j = 0; j < 4; j++)
                    MMA_TF32(acc[i][j], af[cur][i], bf[cur][j]);
        }

        __syncthreads();
        load_stage(c + 3);
    }

    bool vtile = (vT != nullptr) && (col0 >= 2048);

    #pragma unroll
    for (int i = 0; i < 4; i++) {
        int m = row0 + wm * 64 + i * 16 + tg;
        #pragma unroll
        for (int j = 0; j < 4; j++) {
            int n = col0 + wn * 32 + j * 8 + 2 * ti;
            float bx = __ldg(bias + n);
            float by = __ldg(bias + n + 1);
            float v0 = acc[i][j][0] + bx;
            float v1 = acc[i][j][1] + by;
            float v2 = acc[i][j][2] + bx;
            float v3 = acc[i][j][3] + by;
            if (roundC) {
                v0 = to_tf32(v0); v1 = to_tf32(v1);
                v2 = to_tf32(v2); v3 = to_tf32(v3);
            }
            if (vtile) {
                int d0 = n - 2048;
                int t  = m & 2047;
                int bb = m >> 11;
                float* p0 = vT + ((size_t)((bb << 4) | (d0 >> 6)) * 64 + (d0 & 63)) * 2048 + t;
                float* p1 = vT + ((size_t)((bb << 4) | ((d0 + 1) >> 6)) * 64 + ((d0 + 1) & 63)) * 2048 + t;
                p0[0] = v0; p0[8] = v2;
                p1[0] = v1; p1[8] = v3;
            } else {
                *(float2*)&C[(size_t)m * Ntot + n] = make_float2(v0, v1);
                *(float2*)&C[(size_t)(m + 8) * Ntot + n] = make_float2(v2, v3);
            }
        }
    }
}

// ---------------------------------------------------------------------------
// prep kernels
// ---------------------------------------------------------------------------
__global__ __launch_bounds__(256) void cvt4_kernel(
    const float4* __restrict__ in, float4* __restrict__ out, int n4)
{
    int i = blockIdx.x * 256 + threadIdx.x;
    if (i < n4) {
        float4 v = in[i];
        v.x = to_tf32(v.x); v.y = to_tf32(v.y);
        v.z = to_tf32(v.z); v.w = to_tf32(v.w);
        out[i] = v;
    }
}

__global__ __launch_bounds__(256) void transpose_cvt_kernel(
    const float* __restrict__ in, float* __restrict__ out, int R, int C)
{
    __shared__ float t[32][33];
    int c0 = blockIdx.x * 32, r0 = blockIdx.y * 32;
    int tx = threadIdx.x & 31, ty = threadIdx.x >> 5;
    #pragma unroll
    for (int i = ty; i < 32; i += 8)
        t[i][tx] = in[(size_t)(r0 + i) * C + c0 + tx];
    __syncthreads();
    #pragma unroll
    for (int i = ty; i < 32; i += 8)
        out[(size_t)(c0 + i) * R + r0 + tx] = to_tf32(t[tx][i]);
}

// ---------------------------------------------------------------------------
// Tensor-core flash attention (tf32 mma.sync).
// Grid (16, 64): x = q-block (reversed for heavy-first), y = b*16+h.
// 256 threads, 8 warps, warp owns 16 query rows.
// Smem: Qs[128][68] + 2 stages of { Ks[64][68], Vt[64][68] }.
// B-fragments batched ahead of each MMA group for scheduling room.
// ---------------------------------------------------------------------------
#define AS 68
#define ATT_SMEM (384 * AS * 4)

__global__ __launch_bounds__(256, 2) void attn_mma_kernel()
{
    extern __shared__ float sm[];
    uint32_t smemB = smem_to_u32(sm);

    int qb = gridDim.x - 1 - blockIdx.x;       // heavy blocks first
    int bh = blockIdx.y;
    int b = bh >> 4, h = bh & 15;
    int tid = threadIdx.x, lane = tid & 31, warp = tid >> 5;
    int tg = lane >> 2, ti = lane & 3;
    int q0 = qb * 128;
    int kmax = 2 * qb + 1;

    // Q tile -> Qs: 128x64 floats
    {
        #pragma unroll
        for (int u = 0; u < 8; u++) {
            int i = tid + u * 256;
            int r = i >> 4, c4 = (i & 15) * 4;
            const float* src = g_qkv + (size_t)(b * Tsz + q0 + r) * 3072 + h * 64 + c4;
            CP_ASYNC16(smemB + (uint32_t)(r * AS + c4) * 4, src);
        }
        CP_COMMIT();
    }

    auto load_kv = [&](int kb) {
        if (kb <= kmax) {
            uint32_t kB = smemB + (uint32_t)(128 * AS + (kb & 1) * 2 * 64 * AS) * 4;
            #pragma unroll
            for (int u = 0; u < 4; u++) {
                int i = tid + u * 256;
                int r = i >> 4, c4 = (i & 15) * 4;
                const float* kg = g_qkv + (size_t)(b * Tsz + kb * 64 + r) * 3072 + 1024 + h * 64 + c4;
                CP_ASYNC16(kB + (uint32_t)(r * AS + c4) * 4, kg);
                const float* vg = g_vT + ((size_t)bh * 64 + r) * Tsz + kb * 64 + c4;
                CP_ASYNC16(kB + (uint32_t)(64 * AS + r * AS + c4) * 4, vg);
            }
        }
        CP_COMMIT();
    };

    load_kv(0);
    load_kv(1);

    float o[8][4];
    #pragma unroll
    for (int j = 0; j < 8; j++)
        #pragma unroll
        for (int q = 0; q < 4; q++) o[j][q] = 0.f;
    float mr[2] = {-1e30f, -1e30f}, lr[2] = {0.f, 0.f};

    const float* Qs = sm;
    int ra0 = (warp * 16 + tg) * AS;
    int ra1 = ra0 + 8 * AS;

    #pragma unroll 1
    for (int kb = 0; kb <= kmax; kb++) {
        CP_WAIT(1);
        __syncthreads();
        const float* Ks = sm + 128 * AS + (kb & 1) * (2 * 64 * AS);
        const float* Vt = Ks + 64 * AS;

        // ---- S = Q K^T ----
        float s[8][4];
        #pragma unroll
        for (int j = 0; j < 8; j++)
            #pragma unroll
            for (int q = 0; q < 4; q++) s[j][q] = 0.f;

        #pragma unroll
        for (int kt = 0; kt < 8; kt++) {
            int k0 = kt * 8 + ti;
            uint32_t af[4], bk[8][2];
            af[0] = __float_as_uint(Qs[ra0 + k0]);
            af[1] = __float_as_uint(Qs[ra1 + k0]);
            af[2] = __float_as_uint(Qs[ra0 + k0 + 4]);
            af[3] = __float_as_uint(Qs[ra1 + k0 + 4]);
            #pragma unroll
            for (int j = 0; j < 8; j++) {
                bk[j][0] = __float_as_uint(Ks[(j * 8 + tg) * AS + k0]);
                bk[j][1] = __float_as_uint(Ks[(j * 8 + tg) * AS + k0 + 4]);
            }
            #pragma unroll
            for (int j = 0; j < 8; j++)
                MMA_TF32(s[j], af, bk[j]);
        }

        // ---- scale + causal mask ----
        if (kb >= 2 * qb) {
            int row0 = q0 + warp * 16 + tg;
            #pragma unroll
            for (int j = 0; j < 8; j++) {
                int col = kb * 64 + j * 8 + 2 * ti;
                s[j][0] = (col     > row0    ) ? -1e30f : s[j][0] * 0.125f;
                s[j][1] = (col + 1 > row0    ) ? -1e30f : s[j][1] * 0.125f;
                s[j][2] = (col     > row0 + 8) ? -1e30f : s[j][2] * 0.125f;
                s[j][3] = (col + 1 > row0 + 8) ? -1e30f : s[j][3] * 0.125f;
            }
        } else {
            #pragma unroll
            for (int j = 0; j < 8; j++)
                #pragma unroll
                for (int q = 0; q < 4; q++) s[j][q] *= 0.125f;
        }

        // ---- online softmax ----
        float mt0 = -1e30f, mt1 = -1e30f;
        #pragma unroll
        for (int j = 0; j < 8; j++) {
            mt0 = fmaxf(mt0, fmaxf(s[j][0], s[j][1]));
            mt1 = fmaxf(mt1, fmaxf(s[j][2], s[j][3]));
        }
        mt0 = fmaxf(mt0, __shfl_xor_sync(0xffffffffu, mt0, 1));
        mt0 = fmaxf(mt0, __shfl_xor_sync(0xffffffffu, mt0, 2));
        mt1 = fmaxf(mt1, __shfl_xor_sync(0xffffffffu, mt1, 1));
        mt1 = fmaxf(mt1, __shfl_xor_sync(0xffffffffu, mt1, 2));

        float mn0 = fmaxf(mr[0], mt0), mn1 = fmaxf(mr[1], mt1);
        float sc0 = __expf(mr[0] - mn0), sc1 = __expf(mr[1] - mn1);
        float ps0 = 0.f, ps1 = 0.f;
        #pragma unroll
        for (int j = 0; j < 8; j++) {
            s[j][0] = __expf(s[j][0] - mn0); ps0 += s[j][0];
            s[j][1] = __expf(s[j][1] - mn0); ps0 += s[j][1];
            s[j][2] = __expf(s[j][2] - mn1); ps1 += s[j][2];
            s[j][3] = __expf(s[j][3] - mn1); ps1 += s[j][3];
        }
        ps0 += __shfl_xor_sync(0xffffffffu, ps0, 1);
        ps0 += __shfl_xor_sync(0xffffffffu, ps0, 2);
        ps1 += __shfl_xor_sync(0xffffffffu, ps1, 1);
        ps1 += __shfl_xor_sync(0xffffffffu, ps1, 2);
        lr[0] = lr[0] * sc0 + ps0; mr[0] = mn0;
        lr[1] = lr[1] * sc1 + ps1; mr[1] = mn1;

        #pragma unroll
        for (int j = 0; j < 8; j++) {
            o[j][0] *= sc0; o[j][1] *= sc0;
            o[j][2] *= sc1; o[j][3] *= sc1;
            s[j][0] = to_tf32(s[j][0]); s[j][1] = to_tf32(s[j][1]);
            s[j][2] = to_tf32(s[j][2]); s[j][3] = to_tf32(s[j][3]);
        }

        // ---- O += P V ----
        int src0 = (lane & ~3) | (ti >> 1);
        int src1 = src0 + 2;
        bool odd = (ti & 1) != 0;
        #pragma unroll
        for (int kt = 0; kt < 8; kt++) {
            float v00 = __shfl_sync(0xffffffffu, s[kt][0], src0);
            float v01 = __shfl_sync(0xffffffffu, s[kt][1], src0);
            float v02 = __shfl_sync(0xffffffffu, s[kt][2], src0);
            float v03 = __shfl_sync(0xffffffffu, s[kt][3], src0);
            float v10 = __shfl_sync(0xffffffffu, s[kt][0], src1);
            float v11 = __shfl_sync(0xffffffffu, s[kt][1], src1);
            float v12 = __shfl_sync(0xffffffffu, s[kt][2], src1);
            float v13 = __shfl_sync(0xffffffffu, s[kt][3], src1);
            uint32_t af[4], bv[8][2];
            af[0] = __float_as_uint(odd ? v01 : v00);
            af[1] = __float_as_uint(odd ? v03 : v02);
            af[2] = __float_as_uint(odd ? v11 : v10);
            af[3] = __float_as_uint(odd ? v13 : v12);
            int k0 = kt * 8 + ti;
            #pragma unroll
            for (int jd = 0; jd < 8; jd++) {
                bv[jd][0] = __float_as_uint(Vt[(jd * 8 + tg) * AS + k0]);
                bv[jd][1] = __float_as_uint(Vt[(jd * 8 + tg) * AS + k0 + 4]);
            }
            #pragma unroll
            for (int jd = 0; jd < 8; jd++)
                MMA_TF32(o[jd], af, bv[jd]);
        }

        __syncthreads();
        load_kv(kb + 2);
    }

    // ---- epilogue ----
    float i0 = 1.f / lr[0], i1 = 1.f / lr[1];
    size_t m0 = (size_t)(b * Tsz + q0 + warp * 16 + tg);
    #pragma unroll
    for (int jd = 0; jd < 8; jd++) {
        int col = h * 64 + jd * 8 + 2 * ti;
        float2 w0 = make_float2(to_tf32(o[jd][0] * i0), to_tf32(o[jd][1] * i0));
        float2 w1 = make_float2(to_tf32(o[jd][2] * i1), to_tf32(o[jd][3] * i1));
        *(float2*)&g_y[m0 * 1024 + col] = w0;
        *(float2*)&g_y[(m0 + 8) * 1024 + col] = w1;
    }
}

// ---------------------------------------------------------------------------
extern "C" void kernel_launch(void* const* d_in, const int* in_sizes, int n_in,
                              void* d_out, int out_size)
{
    const float* x      = (const float*)d_in[0];
    const float* w_qkv  = (const float*)d_in[1];
    const float* b_qkv  = (const float*)d_in[2];
    const float* w_proj = (const float*)d_in[3];
    const float* b_proj = (const float*)d_in[4];
    float* out = (float*)d_out;

    float* wqkvT; cudaGetSymbolAddress((void**)&wqkvT, g_wqkvT);
    float* wpT;   cudaGetSymbolAddress((void**)&wpT,   g_wpT);
    float* qkv;   cudaGetSymbolAddress((void**)&qkv,   g_qkv);
    float* y;     cudaGetSymbolAddress((void**)&y,     g_y);
    float* xc;    cudaGetSymbolAddress((void**)&xc,    g_xc);
    float* vT;    cudaGetSymbolAddress((void**)&vT,    g_vT);

    // 0) prep: tf32-round x; transpose+round weights
    {
        int n4 = Mrows * Csz / 4;
        cvt4_kernel<<<n4 / 256, 256>>>((const float4*)x, (float4*)xc, n4);
        dim3 g1(3 * Csz / 32, Csz / 32);
        transpose_cvt_kernel<<<g1, 256>>>(w_qkv, wqkvT, Csz, 3 * Csz);
        dim3 g2(Csz / 32, Csz / 32);
        transpose_cvt_kernel<<<g2, 256>>>(w_proj, wpT, Csz, Csz);
    }

    // 1) qkv = x @ w_qkv + b_qkv
    {
        cudaFuncSetAttribute(gemm_mma_kernel,
                             cudaFuncAttributeMaxDynamicSharedMemorySize, GEMM_SMEM);
        dim3 grid(3 * Csz / 128, Mrows / 128);
        gemm_mma_kernel<<<grid, 256, GEMM_SMEM>>>(xc, wqkvT, b_qkv, qkv, 3 * Csz, vT, 1);
    }

    // 2) tensor-core flash attention -> g_y
    {
        cudaFuncSetAttribute(attn_mma_kernel,
                             cudaFuncAttributeMaxDynamicSharedMemorySize, ATT_SMEM);
        dim3 grid(Tsz / 128, Bsz * Hn);
        attn_mma_kernel<<<grid, 256, ATT_SMEM>>>();
    }

    // 3) out = y @ w_proj + b_proj
    {
        dim3 grid(Csz / 128, Mrows / 128);
        gemm_mma_kernel<<<grid, 256, GEMM_SMEM>>>(y, wpT, b_proj, out, Csz, nullptr, 0);
    }
}

// round 7
// speedup vs baseline: 1.0734x; 1.0734x over previous
#include <cuda_runtime.h>
#include <cuda_bf16.h>
#include <cstdint>
#include <cstddef>

#define Bsz   4
#define Tsz   2048
#define Csz   1024
#define Hn    16
#define Dh    64
#define Mrows (Bsz * Tsz)   // 8192

// Scratch (static __device__ arrays — allocation-guard safe)
__device__ float g_qkv [(size_t)Mrows * 3 * Csz];   // [8192, 3072] (q,k thirds used)
__device__ float g_vT  [(size_t)Bsz * Hn * Dh * Tsz]; // [64 bh][64 d][2048 t]
__device__ float g_y   [(size_t)Mrows * Csz];       // [8192, 1024]  (tf32-rounded)
__device__ float g_xc  [(size_t)Mrows * Csz];       // x, tf32-rounded
__device__ float g_wqkvT[(size_t)3 * Csz * Csz];    // [3072, 1024]  (tf32-rounded)
__device__ float g_wpT [(size_t)Csz * Csz];         // [1024, 1024]  (tf32-rounded)

// ---------------------------------------------------------------------------
// Helpers (non-'a' PTX only: cp.async + mma.sync + ldmatrix, sm_80 baseline)
// ---------------------------------------------------------------------------
__device__ __forceinline__ uint32_t smem_to_u32(const void* p) {
    uint32_t a;
    asm("{ .reg .u64 t; cvta.to.shared.u64 t, %1; cvt.u32.u64 %0, t; }"
        : "=r"(a) : "l"(p));
    return a;
}
__device__ __forceinline__ float to_tf32(float x) {
    uint32_t r;
    asm("cvt.rna.tf32.f32 %0, %1;" : "=r"(r) : "f"(x));
    return __uint_as_float(r);
}
__device__ __forceinline__ void ldsm4(uint32_t addr, uint32_t* r) {
    asm volatile("ldmatrix.sync.aligned.m8n8.x4.shared.b16 {%0,%1,%2,%3}, [%4];"
        : "=r"(r[0]), "=r"(r[1]), "=r"(r[2]), "=r"(r[3]) : "r"(addr));
}

#define CP_ASYNC16(dst, src) \
    asm volatile("cp.async.cg.shared.global [%0], [%1], 16;" :: "r"(dst), "l"(src) : "memory")
#define CP_COMMIT() asm volatile("cp.async.commit_group;" ::: "memory")
#define CP_WAIT(n)  asm volatile("cp.async.wait_group %0;" :: "n"(n) : "memory")

// D += A*B, m16n8k8 tf32 (A row-major, B col-major i.e. [n][k])
#define MMA_TF32(d, a, b) \
    asm volatile("mma.sync.aligned.m16n8k8.row.col.f32.tf32.tf32.f32 " \
        "{%0,%1,%2,%3}, {%4,%5,%6,%7}, {%8,%9}, {%0,%1,%2,%3};" \
        : "+f"((d)[0]), "+f"((d)[1]), "+f"((d)[2]), "+f"((d)[3]) \
        : "r"((a)[0]), "r"((a)[1]), "r"((a)[2]), "r"((a)[3]), \
          "r"((b)[0]), "r"((b)[1]))

// ---------------------------------------------------------------------------
// mma.sync tf32 GEMM: C[M,N] = A[M,1024] @ Bt[N,1024]^T + bias
// 128x128 tile, BK=32, 3-stage cp.async, 256 threads, warp tile 64x32.
// Fragments loaded via ldmatrix.x4 (6 LDSM per 16 MMAs).
// If vT != nullptr, tiles with col0 >= 2048 scatter to vT[bh][d][t].
// ---------------------------------------------------------------------------
#define KCHUNKS 32
#define STAGE_F 8192
#define GEMM_SMEM (3 * STAGE_F * 4)

__global__ __launch_bounds__(256) void gemm_mma_kernel(
    const float* __restrict__ A,
    const float* __restrict__ Bt,
    const float* __restrict__ bias,
    float* __restrict__ C,
    int Ntot,
    float* __restrict__ vT,
    int roundC)
{
    extern __shared__ float sm[];
    uint32_t smemB = smem_to_u32(sm);

    int tid  = threadIdx.x;
    int lane = tid & 31;
    int warp = tid >> 5;
    int wm = warp >> 2;
    int wn = warp & 3;
    int tg = lane >> 2;
    int ti = lane & 3;
    int row0 = blockIdx.y * 128;
    int col0 = blockIdx.x * 128;

    // cp.async mapping
    int lr   = tid >> 3;
    int lc4  = (tid & 7) * 4;
    int lswB = (lc4 ^ ((lr & 7) * 4)) * 4;
    const float* gA = A  + (size_t)(row0 + lr) * 1024 + lc4;
    const float* gB = Bt + (size_t)(col0 + lr) * 1024 + lc4;

    // ldmatrix per-lane addressing: tile id t (0..3), row-in-tile rr
    int t_  = lane >> 3;
    int rr  = lane & 7;
    // A frags i=0..3: tiles (kl,m0)(kl,m8)(kh,m0)(kh,m8)
    uint32_t arow[4], axr[4];
    int ach = (t_ >> 1) * 4;
    #pragma unroll
    for (int i = 0; i < 4; i++) {
        int r = wm * 64 + i * 16 + (t_ & 1) * 8 + rr;
        arow[i] = (uint32_t)(r * 128);
        axr[i] = (r & 7) * 4;
    }
    // B frag-pairs p=0..1 (j=2p,2p+1): tiles (j,kl)(j,kh)(j+1,kl)(j+1,kh)
    uint32_t brow[2], bxr[2];
    int bch = (t_ & 1) * 4;
    #pragma unroll
    for (int p = 0; p < 2; p++) {
        int r = wn * 32 + p * 16 + (t_ >> 1) * 8 + rr;
        brow[p] = (uint32_t)(r * 128);
        bxr[p] = (r & 7) * 4;
    }

    float acc[4][4][4];
    #pragma unroll
    for (int i = 0; i < 4; i++)
        #pragma unroll
        for (int j = 0; j < 4; j++)
            #pragma unroll
            for (int q = 0; q < 4; q++) acc[i][j][q] = 0.f;

    auto load_stage = [&](int chunk) {
        if (chunk < KCHUNKS) {
            int s = chunk % 3;
            uint32_t base = smemB + (uint32_t)s * (STAGE_F * 4);
            const float* a = gA + chunk * 32;
            const float* b = gB + chunk * 32;
            #pragma unroll
            for (int j = 0; j < 4; j++) {
                uint32_t off = (uint32_t)((lr + 32 * j) * 128 + lswB);
                CP_ASYNC16(base + off, a + (size_t)j * 32 * 1024);
                CP_ASYNC16(base + 16384 + off, b + (size_t)j * 32 * 1024);
            }
        }
        CP_COMMIT();
    };

    load_stage(0);
    load_stage(1);
    load_stage(2);

    #pragma unroll 1
    for (int c = 0; c < KCHUNKS; ++c) {
        CP_WAIT(2);
        __syncthreads();

        uint32_t AsB = smemB + (uint32_t)(c % 3) * (STAGE_F * 4);
        uint32_t BsB = AsB + 16384;

        #pragma unroll
        for (int ks = 0; ks < 4; ks++) {
            int k0 = ks * 8;
            uint32_t af[4][4], bf[2][4];
            #pragma unroll
            for (int i = 0; i < 4; i++)
                ldsm4(AsB + arow[i] + ((uint32_t)((k0 + ach) ^ axr[i]) << 2), af[i]);
            #pragma unroll
            for (int p = 0; p < 2; p++)
                ldsm4(BsB + brow[p] + ((uint32_t)((k0 + bch) ^ bxr[p]) << 2), bf[p]);
            #pragma unroll
            for (int i = 0; i < 4; i++) {
                MMA_TF32(acc[i][0], af[i], &bf[0][0]);
                MMA_TF32(acc[i][1], af[i], &bf[0][2]);
                MMA_TF32(acc[i][2], af[i], &bf[1][0]);
                MMA_TF32(acc[i][3], af[i], &bf[1][2]);
            }
        }

        __syncthreads();
        load_stage(c + 3);
    }

    bool vtile = (vT != nullptr) && (col0 >= 2048);

    #pragma unroll
    for (int i = 0; i < 4; i++) {
        int m = row0 + wm * 64 + i * 16 + tg;
        #pragma unroll
        for (int j = 0; j < 4; j++) {
            int n = col0 + wn * 32 + j * 8 + 2 * ti;
            float bx = __ldg(bias + n);
            float by = __ldg(bias + n + 1);
            float v0 = acc[i][j][0] + bx;
            float v1 = acc[i][j][1] + by;
            float v2 = acc[i][j][2] + bx;
            float v3 = acc[i][j][3] + by;
            if (roundC) {
                v0 = to_tf32(v0); v1 = to_tf32(v1);
                v2 = to_tf32(v2); v3 = to_tf32(v3);
            }
            if (vtile) {
                int d0 = n - 2048;
                int t  = m & 2047;
                int bb = m >> 11;
                float* p0 = vT + ((size_t)((bb << 4) | (d0 >> 6)) * 64 + (d0 & 63)) * 2048 + t;
                float* p1 = vT + ((size_t)((bb << 4) | ((d0 + 1) >> 6)) * 64 + ((d0 + 1) & 63)) * 2048 + t;
                p0[0] = v0; p0[8] = v2;
                p1[0] = v1; p1[8] = v3;
            } else {
                *(float2*)&C[(size_t)m * Ntot + n] = make_float2(v0, v1);
                *(float2*)&C[(size_t)(m + 8) * Ntot + n] = make_float2(v2, v3);
            }
        }
    }
}

// ---------------------------------------------------------------------------
// prep kernels
// ---------------------------------------------------------------------------
__global__ __launch_bounds__(256) void cvt4_kernel(
    const float4* __restrict__ in, float4* __restrict__ out, int n4)
{
    int i = blockIdx.x * 256 + threadIdx.x;
    if (i < n4) {
        float4 v = in[i];
        v.x = to_tf32(v.x); v.y = to_tf32(v.y);
        v.z = to_tf32(v.z); v.w = to_tf32(v.w);
        out[i] = v;
    }
}

__global__ __launch_bounds__(256) void transpose_cvt_kernel(
    const float* __restrict__ in, float* __restrict__ out, int R, int C)
{
    __shared__ float t[32][33];
    int c0 = blockIdx.x * 32, r0 = blockIdx.y * 32;
    int tx = threadIdx.x & 31, ty = threadIdx.x >> 5;
    #pragma unroll
    for (int i = ty; i < 32; i += 8)
        t[i][tx] = in[(size_t)(r0 + i) * C + c0 + tx];
    __syncthreads();
    #pragma unroll
    for (int i = ty; i < 32; i += 8)
        out[(size_t)(c0 + i) * R + r0 + tx] = to_tf32(t[tx][i]);
}

// ---------------------------------------------------------------------------
// Tensor-core flash attention (tf32 mma.sync + ldmatrix).
// Grid (16, 64): x = q-block (reversed for heavy-first), y = b*16+h.
// 256 threads, 8 warps, warp owns 16 query rows.
// Smem: Qs[128][68] + 2 stages of { Ks[64][68], Vt[64][68] }.
// ---------------------------------------------------------------------------
#define AS 68
#define ATT_SMEM (384 * AS * 4)

__global__ __launch_bounds__(256, 2) void attn_mma_kernel()
{
    extern __shared__ float sm[];
    uint32_t smemB = smem_to_u32(sm);

    int qb = gridDim.x - 1 - blockIdx.x;       // heavy blocks first
    int bh = blockIdx.y;
    int b = bh >> 4, h = bh & 15;
    int tid = threadIdx.x, lane = tid & 31, warp = tid >> 5;
    int tg = lane >> 2, ti = lane & 3;
    int q0 = qb * 128;
    int kmax = 2 * qb + 1;

    // ldmatrix per-lane addressing
    int t_ = lane >> 3, rr = lane & 7;
    // Q frag: tiles (kl,m0)(kl,m8)(kh,m0)(kh,m8)
    uint32_t qoff = (uint32_t)(((warp * 16 + (t_ & 1) * 8 + rr) * AS + (t_ >> 1) * 4) * 4);
    // K/V frag-pairs p=0..3 (j=2p,2p+1): row = 16p + (t>>1)*8 + rr, col = (t&1)*4
    uint32_t kvoff = (uint32_t)((((t_ >> 1) * 8 + rr) * AS + (t_ & 1) * 4) * 4);

    // Q tile -> Qs: 128x64 floats
    {
        #pragma unroll
        for (int u = 0; u < 8; u++) {
            int i = tid + u * 256;
            int r = i >> 4, c4 = (i & 15) * 4;
            const float* src = g_qkv + (size_t)(b * Tsz + q0 + r) * 3072 + h * 64 + c4;
            CP_ASYNC16(smemB + (uint32_t)(r * AS + c4) * 4, src);
        }
        CP_COMMIT();
    }

    auto load_kv = [&](int kb) {
        if (kb <= kmax) {
            uint32_t kB = smemB + (uint32_t)(128 * AS + (kb & 1) * 2 * 64 * AS) * 4;
            #pragma unroll
            for (int u = 0; u < 4; u++) {
                int i = tid + u * 256;
                int r = i >> 4, c4 = (i & 15) * 4;
                const float* kg = g_qkv + (size_t)(b * Tsz + kb * 64 + r) * 3072 + 1024 + h * 64 + c4;
                CP_ASYNC16(kB + (uint32_t)(r * AS + c4) * 4, kg);
                const float* vg = g_vT + ((size_t)bh * 64 + r) * Tsz + kb * 64 + c4;
                CP_ASYNC16(kB + (uint32_t)(64 * AS + r * AS + c4) * 4, vg);
            }
        }
        CP_COMMIT();
    };

    load_kv(0);
    load_kv(1);

    float o[8][4];
    #pragma unroll
    for (int j = 0; j < 8; j++)
        #pragma unroll
        for (int q = 0; q < 4; q++) o[j][q] = 0.f;
    float mr[2] = {-1e30f, -1e30f}, lr[2] = {0.f, 0.f};

    #pragma unroll 1
    for (int kb = 0; kb <= kmax; kb++) {
        CP_WAIT(1);
        __syncthreads();
        uint32_t KsB = smemB + (uint32_t)(128 * AS + (kb & 1) * 2 * 64 * AS) * 4;
        uint32_t VtB = KsB + 64 * AS * 4;

        // ---- S = Q K^T ----
        float s[8][4];
        #pragma unroll
        for (int j = 0; j < 8; j++)
            #pragma unroll
            for (int q = 0; q < 4; q++) s[j][q] = 0.f;

        #pragma unroll
        for (int kt = 0; kt < 8; kt++) {
            uint32_t af[4], bk[4][4];
            ldsm4(smemB + qoff + kt * 32, af);
            #pragma unroll
            for (int p = 0; p < 4; p++)
                ldsm4(KsB + kvoff + (uint32_t)(p * 16 * AS * 4) + kt * 32, bk[p]);
            #pragma unroll
            for (int p = 0; p < 4; p++) {
                MMA_TF32(s[2 * p],     af, &bk[p][0]);
                MMA_TF32(s[2 * p + 1], af, &bk[p][2]);
            }
        }

        // ---- scale + causal mask ----
        if (kb >= 2 * qb) {
            int row0 = q0 + warp * 16 + tg;
            #pragma unroll
            for (int j = 0; j < 8; j++) {
                int col = kb * 64 + j * 8 + 2 * ti;
                s[j][0] = (col     > row0    ) ? -1e30f : s[j][0] * 0.125f;
                s[j][1] = (col + 1 > row0    ) ? -1e30f : s[j][1] * 0.125f;
                s[j][2] = (col     > row0 + 8) ? -1e30f : s[j][2] * 0.125f;
                s[j][3] = (col + 1 > row0 + 8) ? -1e30f : s[j][3] * 0.125f;
            }
        } else {
            #pragma unroll
            for (int j = 0; j < 8; j++)
                #pragma unroll
                for (int q = 0; q < 4; q++) s[j][q] *= 0.125f;
        }

        // ---- online softmax ----
        float mt0 = -1e30f, mt1 = -1e30f;
        #pragma unroll
        for (int j = 0; j < 8; j++) {
            mt0 = fmaxf(mt0, fmaxf(s[j][0], s[j][1]));
            mt1 = fmaxf(mt1, fmaxf(s[j][2], s[j][3]));
        }
        mt0 = fmaxf(mt0, __shfl_xor_sync(0xffffffffu, mt0, 1));
        mt0 = fmaxf(mt0, __shfl_xor_sync(0xffffffffu, mt0, 2));
        mt1 = fmaxf(mt1, __shfl_xor_sync(0xffffffffu, mt1, 1));
        mt1 = fmaxf(mt1, __shfl_xor_sync(0xffffffffu, mt1, 2));

        float mn0 = fmaxf(mr[0], mt0), mn1 = fmaxf(mr[1], mt1);
        float sc0 = __expf(mr[0] - mn0), sc1 = __expf(mr[1] - mn1);
        float ps0 = 0.f, ps1 = 0.f;
        #pragma unroll
        for (int j = 0; j < 8; j++) {
            s[j][0] = __expf(s[j][0] - mn0); ps0 += s[j][0];
            s[j][1] = __expf(s[j][1] - mn0); ps0 += s[j][1];
            s[j][2] = __expf(s[j][2] - mn1); ps1 += s[j][2];
            s[j][3] = __expf(s[j][3] - mn1); ps1 += s[j][3];
        }
        ps0 += __shfl_xor_sync(0xffffffffu, ps0, 1);
        ps0 += __shfl_xor_sync(0xffffffffu, ps0, 2);
        ps1 += __shfl_xor_sync(0xffffffffu, ps1, 1);
        ps1 += __shfl_xor_sync(0xffffffffu, ps1, 2);
        lr[0] = lr[0] * sc0 + ps0; mr[0] = mn0;
        lr[1] = lr[1] * sc1 + ps1; mr[1] = mn1;

        #pragma unroll
        for (int j = 0; j < 8; j++) {
            o[j][0] *= sc0; o[j][1] *= sc0;
            o[j][2] *= sc1; o[j][3] *= sc1;
            s[j][0] = to_tf32(s[j][0]); s[j][1] = to_tf32(s[j][1]);
            s[j][2] = to_tf32(s[j][2]); s[j][3] = to_tf32(s[j][3]);
        }

        // ---- O += P V ----
        int src0 = (lane & ~3) | (ti >> 1);
        int src1 = src0 + 2;
        bool odd = (ti & 1) != 0;
        #pragma unroll
        for (int kt = 0; kt < 8; kt++) {
            float v00 = __shfl_sync(0xffffffffu, s[kt][0], src0);
            float v01 = __shfl_sync(0xffffffffu, s[kt][1], src0);
            float v02 = __shfl_sync(0xffffffffu, s[kt][2], src0);
            float v03 = __shfl_sync(0xffffffffu, s[kt][3], src0);
            float v10 = __shfl_sync(0xffffffffu, s[kt][0], src1);
            float v11 = __shfl_sync(0xffffffffu, s[kt][1], src1);
            float v12 = __shfl_sync(0xffffffffu, s[kt][2], src1);
            float v13 = __shfl_sync(0xffffffffu, s[kt][3], src1);
            uint32_t af[4], bv[4][4];
            af[0] = __float_as_uint(odd ? v01 : v00);
            af[1] = __float_as_uint(odd ? v03 : v02);
            af[2] = __float_as_uint(odd ? v11 : v10);
            af[3] = __float_as_uint(odd ? v13 : v12);
            #pragma unroll
            for (int p = 0; p < 4; p++)
                ldsm4(VtB + kvoff + (uint32_t)(p * 16 * AS * 4) + kt * 32, bv[p]);
            #pragma unroll
            for (int p = 0; p < 4; p++) {
                MMA_TF32(o[2 * p],     af, &bv[p][0]);
                MMA_TF32(o[2 * p + 1], af, &bv[p][2]);
            }
        }

        __syncthreads();
        load_kv(kb + 2);
    }

    // ---- epilogue ----
    float i0 = 1.f / lr[0], i1 = 1.f / lr[1];
    size_t m0 = (size_t)(b * Tsz + q0 + warp * 16 + tg);
    #pragma unroll
    for (int jd = 0; jd < 8; jd++) {
        int col = h * 64 + jd * 8 + 2 * ti;
        float2 w0 = make_float2(to_tf32(o[jd][0] * i0), to_tf32(o[jd][1] * i0));
        float2 w1 = make_float2(to_tf32(o[jd][2] * i1), to_tf32(o[jd][3] * i1));
        *(float2*)&g_y[m0 * 1024 + col] = w0;
        *(float2*)&g_y[(m0 + 8) * 1024 + col] = w1;
    }
}

// ---------------------------------------------------------------------------
extern "C" void kernel_launch(void* const* d_in, const int* in_sizes, int n_in,
                              void* d_out, int out_size)
{
    const float* x      = (const float*)d_in[0];
    const float* w_qkv  = (const float*)d_in[1];
    const float* b_qkv  = (const float*)d_in[2];
    const float* w_proj = (const float*)d_in[3];
    const float* b_proj = (const float*)d_in[4];
    float* out = (float*)d_out;

    float* wqkvT; cudaGetSymbolAddress((void**)&wqkvT, g_wqkvT);
    float* wpT;   cudaGetSymbolAddress((void**)&wpT,   g_wpT);
    float* qkv;   cudaGetSymbolAddress((void**)&qkv,   g_qkv);
    float* y;     cudaGetSymbolAddress((void**)&y,     g_y);
    float* xc;    cudaGetSymbolAddress((void**)&xc,    g_xc);
    float* vT;    cudaGetSymbolAddress((void**)&vT,    g_vT);

    // 0) prep: tf32-round x; transpose+round weights
    {
        int n4 = Mrows * Csz / 4;
        cvt4_kernel<<<n4 / 256, 256>>>((const float4*)x, (float4*)xc, n4);
        dim3 g1(3 * Csz / 32, Csz / 32);
        transpose_cvt_kernel<<<g1, 256>>>(w_qkv, wqkvT, Csz, 3 * Csz);
        dim3 g2(Csz / 32, Csz / 32);
        transpose_cvt_kernel<<<g2, 256>>>(w_proj, wpT, Csz, Csz);
    }

    // 1) qkv = x @ w_qkv + b_qkv
    {
        cudaFuncSetAttribute(gemm_mma_kernel,
                             cudaFuncAttributeMaxDynamicSharedMemorySize, GEMM_SMEM);
        dim3 grid(3 * Csz / 128, Mrows / 128);
        gemm_mma_kernel<<<grid, 256, GEMM_SMEM>>>(xc, wqkvT, b_qkv, qkv, 3 * Csz, vT, 1);
    }

    // 2) tensor-core flash attention -> g_y
    {
        cudaFuncSetAttribute(attn_mma_kernel,
                             cudaFuncAttributeMaxDynamicSharedMemorySize, ATT_SMEM);
        dim3 grid(Tsz / 128, Bsz * Hn);
        attn_mma_kernel<<<grid, 256, ATT_SMEM>>>();
    }

    // 3) out = y @ w_proj + b_proj
    {
        dim3 grid(Csz / 128, Mrows / 128);
        gemm_mma_kernel<<<grid, 256, GEMM_SMEM>>>(y, wpT, b_proj, out, Csz, nullptr, 0);
    }
}

// round 8
// speedup vs baseline: 1.0789x; 1.0051x over previous
#include <cuda_runtime.h>
#include <cuda_bf16.h>
#include <cstdint>
#include <cstddef>

#define Bsz   4
#define Tsz   2048
#define Csz   1024
#define Hn    16
#define Dh    64
#define Mrows (Bsz * Tsz)   // 8192

// 0.125 * log2(e): folded into q so softmax runs in exp2 domain
#define QSCALE 0.18033688011112042f

// Scratch (static __device__ arrays — allocation-guard safe)
__device__ float g_qkv [(size_t)Mrows * 3 * Csz];   // [8192, 3072] (q,k thirds used)
__device__ float g_vT  [(size_t)Bsz * Hn * Dh * Tsz]; // [64 bh][64 d][2048 t]
__device__ float g_y   [(size_t)Mrows * Csz];       // [8192, 1024]  (tf32-rounded)
__device__ float g_xc  [(size_t)Mrows * Csz];       // x, tf32-rounded
__device__ float g_wqkvT[(size_t)3 * Csz * Csz];    // [3072, 1024]  (tf32-rounded)
__device__ float g_wpT [(size_t)Csz * Csz];         // [1024, 1024]  (tf32-rounded)

// ---------------------------------------------------------------------------
// Helpers (non-'a' PTX only: cp.async + mma.sync + ldmatrix, sm_80 baseline)
// ---------------------------------------------------------------------------
__device__ __forceinline__ uint32_t smem_to_u32(const void* p) {
    uint32_t a;
    asm("{ .reg .u64 t; cvta.to.shared.u64 t, %1; cvt.u32.u64 %0, t; }"
        : "=r"(a) : "l"(p));
    return a;
}
__device__ __forceinline__ float to_tf32(float x) {
    uint32_t r;
    asm("cvt.rna.tf32.f32 %0, %1;" : "=r"(r) : "f"(x));
    return __uint_as_float(r);
}
__device__ __forceinline__ float ex2(float x) {
    float r;
    asm("ex2.approx.f32 %0, %1;" : "=f"(r) : "f"(x));
    return r;
}
__device__ __forceinline__ void ldsm4(uint32_t addr, uint32_t* r) {
    asm volatile("ldmatrix.sync.aligned.m8n8.x4.shared.b16 {%0,%1,%2,%3}, [%4];"
        : "=r"(r[0]), "=r"(r[1]), "=r"(r[2]), "=r"(r[3]) : "r"(addr));
}

#define CP_ASYNC16(dst, src) \
    asm volatile("cp.async.cg.shared.global [%0], [%1], 16;" :: "r"(dst), "l"(src) : "memory")
#define CP_COMMIT() asm volatile("cp.async.commit_group;" ::: "memory")
#define CP_WAIT(n)  asm volatile("cp.async.wait_group %0;" :: "n"(n) : "memory")

// D += A*B, m16n8k8 tf32 (A row-major, B col-major i.e. [n][k])
#define MMA_TF32(d, a, b) \
    asm volatile("mma.sync.aligned.m16n8k8.row.col.f32.tf32.tf32.f32 " \
        "{%0,%1,%2,%3}, {%4,%5,%6,%7}, {%8,%9}, {%0,%1,%2,%3};" \
        : "+f"((d)[0]), "+f"((d)[1]), "+f"((d)[2]), "+f"((d)[3]) \
        : "r"((a)[0]), "r"((a)[1]), "r"((a)[2]), "r"((a)[3]), \
          "r"((b)[0]), "r"((b)[1]))

// ---------------------------------------------------------------------------
// mma.sync tf32 GEMM: C[M,N] = A[M,1024] @ Bt[N,1024]^T + bias
// 128x128 tile, BK=32, 3-stage cp.async, SINGLE sync per chunk.
// Fragments via ldmatrix.x4. vT: scatter V third; also pre-scales q third.
// ---------------------------------------------------------------------------
#define KCHUNKS 32
#define STAGE_F 8192
#define GEMM_SMEM (3 * STAGE_F * 4)

__global__ __launch_bounds__(256) void gemm_mma_kernel(
    const float* __restrict__ A,
    const float* __restrict__ Bt,
    const float* __restrict__ bias,
    float* __restrict__ C,
    int Ntot,
    float* __restrict__ vT,
    int roundC)
{
    extern __shared__ float sm[];
    uint32_t smemB = smem_to_u32(sm);

    int tid  = threadIdx.x;
    int lane = tid & 31;
    int warp = tid >> 5;
    int wm = warp >> 2;
    int wn = warp & 3;
    int tg = lane >> 2;
    int ti = lane & 3;
    int row0 = blockIdx.y * 128;
    int col0 = blockIdx.x * 128;

    // cp.async mapping
    int lr   = tid >> 3;
    int lc4  = (tid & 7) * 4;
    int lswB = (lc4 ^ ((lr & 7) * 4)) * 4;
    const float* gA = A  + (size_t)(row0 + lr) * 1024 + lc4;
    const float* gB = Bt + (size_t)(col0 + lr) * 1024 + lc4;

    // ldmatrix per-lane addressing
    int t_  = lane >> 3;
    int rr  = lane & 7;
    uint32_t arow[4], axr[4];
    int ach = (t_ >> 1) * 4;
    #pragma unroll
    for (int i = 0; i < 4; i++) {
        int r = wm * 64 + i * 16 + (t_ & 1) * 8 + rr;
        arow[i] = (uint32_t)(r * 128);
        axr[i] = (r & 7) * 4;
    }
    uint32_t brow[2], bxr[2];
    int bch = (t_ & 1) * 4;
    #pragma unroll
    for (int p = 0; p < 2; p++) {
        int r = wn * 32 + p * 16 + (t_ >> 1) * 8 + rr;
        brow[p] = (uint32_t)(r * 128);
        bxr[p] = (r & 7) * 4;
    }

    float acc[4][4][4];
    #pragma unroll
    for (int i = 0; i < 4; i++)
        #pragma unroll
        for (int j = 0; j < 4; j++)
            #pragma unroll
            for (int q = 0; q < 4; q++) acc[i][j][q] = 0.f;

    auto load_stage = [&](int chunk) {
        if (chunk < KCHUNKS) {
            int s = chunk % 3;
            uint32_t base = smemB + (uint32_t)s * (STAGE_F * 4);
            const float* a = gA + chunk * 32;
            const float* b = gB + chunk * 32;
            #pragma unroll
            for (int j = 0; j < 4; j++) {
                uint32_t off = (uint32_t)((lr + 32 * j) * 128 + lswB);
                CP_ASYNC16(base + off, a + (size_t)j * 32 * 1024);
                CP_ASYNC16(base + 16384 + off, b + (size_t)j * 32 * 1024);
            }
        }
        CP_COMMIT();
    };

    load_stage(0);
    load_stage(1);

    #pragma unroll 1
    for (int c = 0; c < KCHUNKS; ++c) {
        CP_WAIT(1);
        __syncthreads();
        load_stage(c + 2);   // targets (c+2)%3: protected by the barrier above

        uint32_t AsB = smemB + (uint32_t)(c % 3) * (STAGE_F * 4);
        uint32_t BsB = AsB + 16384;

        #pragma unroll
        for (int ks = 0; ks < 4; ks++) {
            int k0 = ks * 8;
            uint32_t af[4][4], bf[2][4];
            #pragma unroll
            for (int i = 0; i < 4; i++)
                ldsm4(AsB + arow[i] + ((uint32_t)((k0 + ach) ^ axr[i]) << 2), af[i]);
            #pragma unroll
            for (int p = 0; p < 2; p++)
                ldsm4(BsB + brow[p] + ((uint32_t)((k0 + bch) ^ bxr[p]) << 2), bf[p]);
            #pragma unroll
            for (int i = 0; i < 4; i++) {
                MMA_TF32(acc[i][0], af[i], &bf[0][0]);
                MMA_TF32(acc[i][1], af[i], &bf[0][2]);
                MMA_TF32(acc[i][2], af[i], &bf[1][0]);
                MMA_TF32(acc[i][3], af[i], &bf[1][2]);
            }
        }
    }

    bool vtile = (vT != nullptr) && (col0 >= 2048);
    float outsc = (vT != nullptr && col0 < 1024) ? QSCALE : 1.0f;  // q pre-scale

    #pragma unroll
    for (int i = 0; i < 4; i++) {
        int m = row0 + wm * 64 + i * 16 + tg;
        #pragma unroll
        for (int j = 0; j < 4; j++) {
            int n = col0 + wn * 32 + j * 8 + 2 * ti;
            float bx = __ldg(bias + n);
            float by = __ldg(bias + n + 1);
            float v0 = (acc[i][j][0] + bx) * outsc;
            float v1 = (acc[i][j][1] + by) * outsc;
            float v2 = (acc[i][j][2] + bx) * outsc;
            float v3 = (acc[i][j][3] + by) * outsc;
            if (roundC) {
                v0 = to_tf32(v0); v1 = to_tf32(v1);
                v2 = to_tf32(v2); v3 = to_tf32(v3);
            }
            if (vtile) {
                int d0 = n - 2048;
                int t  = m & 2047;
                int bb = m >> 11;
                float* p0 = vT + ((size_t)((bb << 4) | (d0 >> 6)) * 64 + (d0 & 63)) * 2048 + t;
                float* p1 = vT + ((size_t)((bb << 4) | ((d0 + 1) >> 6)) * 64 + ((d0 + 1) & 63)) * 2048 + t;
                p0[0] = v0; p0[8] = v2;
                p1[0] = v1; p1[8] = v3;
            } else {
                *(float2*)&C[(size_t)m * Ntot + n] = make_float2(v0, v1);
                *(float2*)&C[(size_t)(m + 8) * Ntot + n] = make_float2(v2, v3);
            }
        }
    }
}

// ---------------------------------------------------------------------------
// prep kernels
// ---------------------------------------------------------------------------
__global__ __launch_bounds__(256) void cvt4_kernel(
    const float4* __restrict__ in, float4* __restrict__ out, int n4)
{
    int i = blockIdx.x * 256 + threadIdx.x;
    if (i < n4) {
        float4 v = in[i];
        v.x = to_tf32(v.x); v.y = to_tf32(v.y);
        v.z = to_tf32(v.z); v.w = to_tf32(v.w);
        out[i] = v;
    }
}

__global__ __launch_bounds__(256) void transpose_cvt_kernel(
    const float* __restrict__ in, float* __restrict__ out, int R, int C)
{
    __shared__ float t[32][33];
    int c0 = blockIdx.x * 32, r0 = blockIdx.y * 32;
    int tx = threadIdx.x & 31, ty = threadIdx.x >> 5;
    #pragma unroll
    for (int i = ty; i < 32; i += 8)
        t[i][tx] = in[(size_t)(r0 + i) * C + c0 + tx];
    __syncthreads();
    #pragma unroll
    for (int i = ty; i < 32; i += 8)
        out[(size_t)(c0 + i) * R + r0 + tx] = to_tf32(t[tx][i]);
}

// ---------------------------------------------------------------------------
// Tensor-core flash attention (tf32 mma.sync + ldmatrix).
// Q pre-scaled by 0.125*log2(e) -> softmax in exp2 domain.
// SINGLE sync per K-block (2-stage KV, prefetch distance 1).
// ---------------------------------------------------------------------------
#define AS 68
#define ATT_SMEM (384 * AS * 4)

__global__ __launch_bounds__(256, 2) void attn_mma_kernel()
{
    extern __shared__ float sm[];
    uint32_t smemB = smem_to_u32(sm);

    int qb = gridDim.x - 1 - blockIdx.x;       // heavy blocks first
    int bh = blockIdx.y;
    int b = bh >> 4, h = bh & 15;
    int tid = threadIdx.x, lane = tid & 31, warp = tid >> 5;
    int tg = lane >> 2, ti = lane & 3;
    int q0 = qb * 128;
    int kmax = 2 * qb + 1;

    // ldmatrix per-lane addressing
    int t_ = lane >> 3, rr = lane & 7;
    uint32_t qoff = (uint32_t)(((warp * 16 + (t_ & 1) * 8 + rr) * AS + (t_ >> 1) * 4) * 4);
    uint32_t kvoff = (uint32_t)((((t_ >> 1) * 8 + rr) * AS + (t_ & 1) * 4) * 4);

    // Q tile -> Qs (in the group with load_kv(0))
    {
        #pragma unroll
        for (int u = 0; u < 8; u++) {
            int i = tid + u * 256;
            int r = i >> 4, c4 = (i & 15) * 4;
            const float* src = g_qkv + (size_t)(b * Tsz + q0 + r) * 3072 + h * 64 + c4;
            CP_ASYNC16(smemB + (uint32_t)(r * AS + c4) * 4, src);
        }
    }

    auto load_kv = [&](int kb) {
        if (kb <= kmax) {
            uint32_t kB = smemB + (uint32_t)(128 * AS + (kb & 1) * 2 * 64 * AS) * 4;
            #pragma unroll
            for (int u = 0; u < 4; u++) {
                int i = tid + u * 256;
                int r = i >> 4, c4 = (i & 15) * 4;
                const float* kg = g_qkv + (size_t)(b * Tsz + kb * 64 + r) * 3072 + 1024 + h * 64 + c4;
                CP_ASYNC16(kB + (uint32_t)(r * AS + c4) * 4, kg);
                const float* vg = g_vT + ((size_t)bh * 64 + r) * Tsz + kb * 64 + c4;
                CP_ASYNC16(kB + (uint32_t)(64 * AS + r * AS + c4) * 4, vg);
            }
        }
        CP_COMMIT();
    };

    load_kv(0);   // includes Q in its group

    float o[8][4];
    #pragma unroll
    for (int j = 0; j < 8; j++)
        #pragma unroll
        for (int q = 0; q < 4; q++) o[j][q] = 0.f;
    float mr[2] = {-1e30f, -1e30f}, lr[2] = {0.f, 0.f};

    #pragma unroll 1
    for (int kb = 0; kb <= kmax; kb++) {
        CP_WAIT(0);
        __syncthreads();
        load_kv(kb + 1);   // other stage; previous readers cleared by barrier

        uint32_t KsB = smemB + (uint32_t)(128 * AS + (kb & 1) * 2 * 64 * AS) * 4;
        uint32_t VtB = KsB + 64 * AS * 4;

        // ---- S = Q K^T (log2-domain: Q pre-scaled) ----
        float s[8][4];
        #pragma unroll
        for (int j = 0; j < 8; j++)
            #pragma unroll
            for (int q = 0; q < 4; q++) s[j][q] = 0.f;

        #pragma unroll
        for (int kt = 0; kt < 8; kt++) {
            uint32_t af[4], bk[4][4];
            ldsm4(smemB + qoff + kt * 32, af);
            #pragma unroll
            for (int p = 0; p < 4; p++)
                ldsm4(KsB + kvoff + (uint32_t)(p * 16 * AS * 4) + kt * 32, bk[p]);
            #pragma unroll
            for (int p = 0; p < 4; p++) {
                MMA_TF32(s[2 * p],     af, &bk[p][0]);
                MMA_TF32(s[2 * p + 1], af, &bk[p][2]);
            }
        }

        // ---- causal mask (no scaling needed) ----
        if (kb >= 2 * qb) {
            int row0 = q0 + warp * 16 + tg;
            #pragma unroll
            for (int j = 0; j < 8; j++) {
                int col = kb * 64 + j * 8 + 2 * ti;
                if (col     > row0    ) s[j][0] = -1e30f;
                if (col + 1 > row0    ) s[j][1] = -1e30f;
                if (col     > row0 + 8) s[j][2] = -1e30f;
                if (col + 1 > row0 + 8) s[j][3] = -1e30f;
            }
        }

        // ---- online softmax (exp2 domain) ----
        float mt0 = -1e30f, mt1 = -1e30f;
        #pragma unroll
        for (int j = 0; j < 8; j++) {
            mt0 = fmaxf(mt0, fmaxf(s[j][0], s[j][1]));
            mt1 = fmaxf(mt1, fmaxf(s[j][2], s[j][3]));
        }
        mt0 = fmaxf(mt0, __shfl_xor_sync(0xffffffffu, mt0, 1));
        mt0 = fmaxf(mt0, __shfl_xor_sync(0xffffffffu, mt0, 2));
        mt1 = fmaxf(mt1, __shfl_xor_sync(0xffffffffu, mt1, 1));
        mt1 = fmaxf(mt1, __shfl_xor_sync(0xffffffffu, mt1, 2));

        float mn0 = fmaxf(mr[0], mt0), mn1 = fmaxf(mr[1], mt1);
        float sc0 = ex2(mr[0] - mn0), sc1 = ex2(mr[1] - mn1);
        float ps0 = 0.f, ps1 = 0.f;
        #pragma unroll
        for (int j = 0; j < 8; j++) {
            s[j][0] = ex2(s[j][0] - mn0); ps0 += s[j][0];
            s[j][1] = ex2(s[j][1] - mn0); ps0 += s[j][1];
            s[j][2] = ex2(s[j][2] - mn1); ps1 += s[j][2];
            s[j][3] = ex2(s[j][3] - mn1); ps1 += s[j][3];
        }
        ps0 += __shfl_xor_sync(0xffffffffu, ps0, 1);
        ps0 += __shfl_xor_sync(0xffffffffu, ps0, 2);
        ps1 += __shfl_xor_sync(0xffffffffu, ps1, 1);
        ps1 += __shfl_xor_sync(0xffffffffu, ps1, 2);
        lr[0] = lr[0] * sc0 + ps0; mr[0] = mn0;
        lr[1] = lr[1] * sc1 + ps1; mr[1] = mn1;

        #pragma unroll
        for (int j = 0; j < 8; j++) {
            o[j][0] *= sc0; o[j][1] *= sc0;
            o[j][2] *= sc1; o[j][3] *= sc1;
            s[j][0] = to_tf32(s[j][0]); s[j][1] = to_tf32(s[j][1]);
            s[j][2] = to_tf32(s[j][2]); s[j][3] = to_tf32(s[j][3]);
        }

        // ---- O += P V ----
        int src0 = (lane & ~3) | (ti >> 1);
        int src1 = src0 + 2;
        bool odd = (ti & 1) != 0;
        #pragma unroll
        for (int kt = 0; kt < 8; kt++) {
            float v00 = __shfl_sync(0xffffffffu, s[kt][0], src0);
            float v01 = __shfl_sync(0xffffffffu, s[kt][1], src0);
            float v02 = __shfl_sync(0xffffffffu, s[kt][2], src0);
            float v03 = __shfl_sync(0xffffffffu, s[kt][3], src0);
            float v10 = __shfl_sync(0xffffffffu, s[kt][0], src1);
            float v11 = __shfl_sync(0xffffffffu, s[kt][1], src1);
            float v12 = __shfl_sync(0xffffffffu, s[kt][2], src1);
            float v13 = __shfl_sync(0xffffffffu, s[kt][3], src1);
            uint32_t af[4], bv[4][4];
            af[0] = __float_as_uint(odd ? v01 : v00);
            af[1] = __float_as_uint(odd ? v03 : v02);
            af[2] = __float_as_uint(odd ? v11 : v10);
            af[3] = __float_as_uint(odd ? v13 : v12);
            #pragma unroll
            for (int p = 0; p < 4; p++)
                ldsm4(VtB + kvoff + (uint32_t)(p * 16 * AS * 4) + kt * 32, bv[p]);
            #pragma unroll
            for (int p = 0; p < 4; p++) {
                MMA_TF32(o[2 * p],     af, &bv[p][0]);
                MMA_TF32(o[2 * p + 1], af, &bv[p][2]);
            }
        }
    }

    // ---- epilogue ----
    float i0 = 1.f / lr[0], i1 = 1.f / lr[1];
    size_t m0 = (size_t)(b * Tsz + q0 + warp * 16 + tg);
    #pragma unroll
    for (int jd = 0; jd < 8; jd++) {
        int col = h * 64 + jd * 8 + 2 * ti;
        float2 w0 = make_float2(to_tf32(o[jd][0] * i0), to_tf32(o[jd][1] * i0));
        float2 w1 = make_float2(to_tf32(o[jd][2] * i1), to_tf32(o[jd][3] * i1));
        *(float2*)&g_y[m0 * 1024 + col] = w0;
        *(float2*)&g_y[(m0 + 8) * 1024 + col] = w1;
    }
}

// ---------------------------------------------------------------------------
extern "C" void kernel_launch(void* const* d_in, const int* in_sizes, int n_in,
                              void* d_out, int out_size)
{
    const float* x      = (const float*)d_in[0];
    const float* w_qkv  = (const float*)d_in[1];
    const float* b_qkv  = (const float*)d_in[2];
    const float* w_proj = (const float*)d_in[3];
    const float* b_proj = (const float*)d_in[4];
    float* out = (float*)d_out;

    float* wqkvT; cudaGetSymbolAddress((void**)&wqkvT, g_wqkvT);
    float* wpT;   cudaGetSymbolAddress((void**)&wpT,   g_wpT);
    float* qkv;   cudaGetSymbolAddress((void**)&qkv,   g_qkv);
    float* y;     cudaGetSymbolAddress((void**)&y,     g_y);
    float* xc;    cudaGetSymbolAddress((void**)&xc,    g_xc);
    float* vT;    cudaGetSymbolAddress((void**)&vT,    g_vT);

    // 0) prep: tf32-round x; transpose+round weights
    {
        int n4 = Mrows * Csz / 4;
        cvt4_kernel<<<n4 / 256, 256>>>((const float4*)x, (float4*)xc, n4);
        dim3 g1(3 * Csz / 32, Csz / 32);
        transpose_cvt_kernel<<<g1, 256>>>(w_qkv, wqkvT, Csz, 3 * Csz);
        dim3 g2(Csz / 32, Csz / 32);
        transpose_cvt_kernel<<<g2, 256>>>(w_proj, wpT, Csz, Csz);
    }

    // 1) qkv = x @ w_qkv + b_qkv   (q pre-scaled, v scattered to vT, rounded)
    {
        cudaFuncSetAttribute(gemm_mma_kernel,
                             cudaFuncAttributeMaxDynamicSharedMemorySize, GEMM_SMEM);
        dim3 grid(3 * Csz / 128, Mrows / 128);
        gemm_mma_kernel<<<grid, 256, GEMM_SMEM>>>(xc, wqkvT, b_qkv, qkv, 3 * Csz, vT, 1);
    }

    // 2) tensor-core flash attention -> g_y
    {
        cudaFuncSetAttribute(attn_mma_kernel,
                             cudaFuncAttributeMaxDynamicSharedMemorySize, ATT_SMEM);
        dim3 grid(Tsz / 128, Bsz * Hn);
        attn_mma_kernel<<<grid, 256, ATT_SMEM>>>();
    }

    // 3) out = y @ w_proj + b_proj
    {
        dim3 grid(Csz / 128, Mrows / 128);
        gemm_mma_kernel<<<grid, 256, GEMM_SMEM>>>(y, wpT, b_proj, out, Csz, nullptr, 0);
    }
}

// round 9
// speedup vs baseline: 1.1532x; 1.0689x over previous
#include <cuda_runtime.h>
#include <cuda_bf16.h>
#include <cstdint>
#include <cstddef>

#define Bsz   4
#define Tsz   2048
#define Csz   1024
#define Hn    16
#define Dh    64
#define Mrows (Bsz * Tsz)   // 8192

// 0.125 * log2(e): folded into q so softmax runs in exp2 domain
#define QSCALE 0.18033688011112042f

// Scratch (static __device__ arrays — allocation-guard safe)
__device__ float g_qkv [(size_t)Mrows * 3 * Csz];   // [8192, 3072] (q,k thirds used)
__device__ float g_vT  [(size_t)Bsz * Hn * Dh * Tsz]; // [64 bh][64 d][2048 t]
__device__ float g_y   [(size_t)Mrows * Csz];       // [8192, 1024]  (tf32-rounded)
__device__ float g_xc  [(size_t)Mrows * Csz];       // x, tf32-rounded
__device__ float g_wqkvT[(size_t)3 * Csz * Csz];    // [3072, 1024]  (tf32-rounded)
__device__ float g_wpT [(size_t)Csz * Csz];         // [1024, 1024]  (tf32-rounded)

// ---------------------------------------------------------------------------
// Helpers (non-'a' PTX only: cp.async + mma.sync + ldmatrix, sm_80 baseline)
// ---------------------------------------------------------------------------
__device__ __forceinline__ uint32_t smem_to_u32(const void* p) {
    uint32_t a;
    asm("{ .reg .u64 t; cvta.to.shared.u64 t, %1; cvt.u32.u64 %0, t; }"
        : "=r"(a) : "l"(p));
    return a;
}
__device__ __forceinline__ float to_tf32(float x) {
    uint32_t r;
    asm("cvt.rna.tf32.f32 %0, %1;" : "=r"(r) : "f"(x));
    return __uint_as_float(r);
}
__device__ __forceinline__ float ex2(float x) {
    float r;
    asm("ex2.approx.f32 %0, %1;" : "=f"(r) : "f"(x));
    return r;
}
__device__ __forceinline__ void ldsm4(uint32_t addr, uint32_t* r) {
    asm volatile("ldmatrix.sync.aligned.m8n8.x4.shared.b16 {%0,%1,%2,%3}, [%4];"
        : "=r"(r[0]), "=r"(r[1]), "=r"(r[2]), "=r"(r[3]) : "r"(addr));
}

#define CP_ASYNC16(dst, src) \
    asm volatile("cp.async.cg.shared.global [%0], [%1], 16;" :: "r"(dst), "l"(src) : "memory")
#define CP_COMMIT() asm volatile("cp.async.commit_group;" ::: "memory")
#define CP_WAIT(n)  asm volatile("cp.async.wait_group %0;" :: "n"(n) : "memory")

// D += A*B, m16n8k8 tf32 (A row-major, B col-major i.e. [n][k])
#define MMA_TF32(d, a, b) \
    asm volatile("mma.sync.aligned.m16n8k8.row.col.f32.tf32.tf32.f32 " \
        "{%0,%1,%2,%3}, {%4,%5,%6,%7}, {%8,%9}, {%0,%1,%2,%3};" \
        : "+f"((d)[0]), "+f"((d)[1]), "+f"((d)[2]), "+f"((d)[3]) \
        : "r"((a)[0]), "r"((a)[1]), "r"((a)[2]), "r"((a)[3]), \
          "r"((b)[0]), "r"((b)[1]))

// ---------------------------------------------------------------------------
// mma.sync tf32 GEMM: C[M,N] = A[M,1024] @ Bt[N,1024]^T + bias
// 128x128 CTA tile, BK=32, 3-stage cp.async, 128 threads (2x2 warps),
// warp tile 64x64 (16.4 FLOP per smem byte read). Single sync per chunk.
// ---------------------------------------------------------------------------
#define KCHUNKS 32
#define STAGE_F 8192
#define GEMM_SMEM (3 * STAGE_F * 4)

__global__ __launch_bounds__(128, 2) void gemm_mma_kernel(
    const float* __restrict__ A,
    const float* __restrict__ Bt,
    const float* __restrict__ bias,
    float* __restrict__ C,
    int Ntot,
    float* __restrict__ vT,
    int roundC)
{
    extern __shared__ float sm[];
    uint32_t smemB = smem_to_u32(sm);

    int tid  = threadIdx.x;
    int lane = tid & 31;
    int warp = tid >> 5;         // 0..3
    int wm = warp >> 1;          // 0..1
    int wn = warp & 1;           // 0..1
    int tg = lane >> 2;
    int ti = lane & 3;
    int row0 = blockIdx.y * 128;
    int col0 = blockIdx.x * 128;

    // cp.async mapping: 128 threads, 8 j-iters of 16 rows (16 % 8 == 0: swizzle fixed)
    int lr   = tid >> 3;                    // 0..15
    int lc4  = (tid & 7) * 4;
    int lswB = (lc4 ^ ((lr & 7) * 4)) * 4;
    const float* gA = A  + (size_t)(row0 + lr) * 1024 + lc4;
    const float* gB = Bt + (size_t)(col0 + lr) * 1024 + lc4;

    // ldmatrix per-lane addressing (identical tile pattern to round-7, extended)
    int t_  = lane >> 3;
    int rr  = lane & 7;
    uint32_t arow[4], axr[4];
    int ach = (t_ >> 1) * 4;
    #pragma unroll
    for (int i = 0; i < 4; i++) {
        int r = wm * 64 + i * 16 + (t_ & 1) * 8 + rr;
        arow[i] = (uint32_t)(r * 128);
        axr[i] = (r & 7) * 4;
    }
    uint32_t brow[4], bxr[4];
    int bch = (t_ & 1) * 4;
    #pragma unroll
    for (int p = 0; p < 4; p++) {
        int r = wn * 64 + p * 16 + (t_ >> 1) * 8 + rr;
        brow[p] = (uint32_t)(r * 128);
        bxr[p] = (r & 7) * 4;
    }

    float acc[4][8][4];
    #pragma unroll
    for (int i = 0; i < 4; i++)
        #pragma unroll
        for (int j = 0; j < 8; j++)
            #pragma unroll
            for (int q = 0; q < 4; q++) acc[i][j][q] = 0.f;

    auto load_stage = [&](int chunk) {
        if (chunk < KCHUNKS) {
            int s = chunk % 3;
            uint32_t base = smemB + (uint32_t)s * (STAGE_F * 4);
            const float* a = gA + chunk * 32;
            const float* b = gB + chunk * 32;
            #pragma unroll
            for (int j = 0; j < 8; j++) {
                uint32_t off = (uint32_t)((lr + 16 * j) * 128 + lswB);
                CP_ASYNC16(base + off, a + (size_t)j * 16 * 1024);
                CP_ASYNC16(base + 16384 + off, b + (size_t)j * 16 * 1024);
            }
        }
        CP_COMMIT();
    };

    load_stage(0);
    load_stage(1);

    #pragma unroll 1
    for (int c = 0; c < KCHUNKS; ++c) {
        CP_WAIT(1);
        __syncthreads();
        load_stage(c + 2);   // (c+2)%3: protected by the barrier above

        uint32_t AsB = smemB + (uint32_t)(c % 3) * (STAGE_F * 4);
        uint32_t BsB = AsB + 16384;

        #pragma unroll
        for (int ks = 0; ks < 4; ks++) {
            int k0 = ks * 8;
            uint32_t af[4][4], bf[4][4];
            #pragma unroll
            for (int i = 0; i < 4; i++)
                ldsm4(AsB + arow[i] + ((uint32_t)((k0 + ach) ^ axr[i]) << 2), af[i]);
            #pragma unroll
            for (int p = 0; p < 4; p++)
                ldsm4(BsB + brow[p] + ((uint32_t)((k0 + bch) ^ bxr[p]) << 2), bf[p]);
            #pragma unroll
            for (int i = 0; i < 4; i++)
                #pragma unroll
                for (int p = 0; p < 4; p++) {
                    MMA_TF32(acc[i][2 * p],     af[i], &bf[p][0]);
                    MMA_TF32(acc[i][2 * p + 1], af[i], &bf[p][2]);
                }
        }
    }

    bool vtile = (vT != nullptr) && (col0 >= 2048);
    float outsc = (vT != nullptr && col0 < 1024) ? QSCALE : 1.0f;  // q pre-scale

    #pragma unroll
    for (int i = 0; i < 4; i++) {
        int m = row0 + wm * 64 + i * 16 + tg;
        #pragma unroll
        for (int j = 0; j < 8; j++) {
            int n = col0 + wn * 64 + j * 8 + 2 * ti;
            float bx = __ldg(bias + n);
            float by = __ldg(bias + n + 1);
            float v0 = (acc[i][j][0] + bx) * outsc;
            float v1 = (acc[i][j][1] + by) * outsc;
            float v2 = (acc[i][j][2] + bx) * outsc;
            float v3 = (acc[i][j][3] + by) * outsc;
            if (roundC) {
                v0 = to_tf32(v0); v1 = to_tf32(v1);
                v2 = to_tf32(v2); v3 = to_tf32(v3);
            }
            if (vtile) {
                int d0 = n - 2048;
                int t  = m & 2047;
                int bb = m >> 11;
                float* p0 = vT + ((size_t)((bb << 4) | (d0 >> 6)) * 64 + (d0 & 63)) * 2048 + t;
                float* p1 = vT + ((size_t)((bb << 4) | ((d0 + 1) >> 6)) * 64 + ((d0 + 1) & 63)) * 2048 + t;
                p0[0] = v0; p0[8] = v2;
                p1[0] = v1; p1[8] = v3;
            } else {
                *(float2*)&C[(size_t)m * Ntot + n] = make_float2(v0, v1);
                *(float2*)&C[(size_t)(m + 8) * Ntot + n] = make_float2(v2, v3);
            }
        }
    }
}

// ---------------------------------------------------------------------------
// prep kernels
// ---------------------------------------------------------------------------
__global__ __launch_bounds__(256) void cvt4_kernel(
    const float4* __restrict__ in, float4* __restrict__ out, int n4)
{
    int i = blockIdx.x * 256 + threadIdx.x;
    if (i < n4) {
        float4 v = in[i];
        v.x = to_tf32(v.x); v.y = to_tf32(v.y);
        v.z = to_tf32(v.z); v.w = to_tf32(v.w);
        out[i] = v;
    }
}

__global__ __launch_bounds__(256) void transpose_cvt_kernel(
    const float* __restrict__ in, float* __restrict__ out, int R, int C)
{
    __shared__ float t[32][33];
    int c0 = blockIdx.x * 32, r0 = blockIdx.y * 32;
    int tx = threadIdx.x & 31, ty = threadIdx.x >> 5;
    #pragma unroll
    for (int i = ty; i < 32; i += 8)
        t[i][tx] = in[(size_t)(r0 + i) * C + c0 + tx];
    __syncthreads();
    #pragma unroll
    for (int i = ty; i < 32; i += 8)
        out[(size_t)(c0 + i) * R + r0 + tx] = to_tf32(t[tx][i]);
}

// ---------------------------------------------------------------------------
// Tensor-core flash attention (tf32 mma.sync + ldmatrix).
// 128 threads, 4 warps, warp tile m32 x n64 (2x FLOP per smem byte).
// Q pre-scaled -> exp2-domain softmax. Single sync per K-block.
// ---------------------------------------------------------------------------
#define AS 68
#define ATT_SMEM (384 * AS * 4)   // Q 128 rows + 2 stages of (K 64 + V 64)

__global__ __launch_bounds__(128, 2) void attn_mma_kernel()
{
    extern __shared__ float sm[];
    uint32_t smemB = smem_to_u32(sm);

    int qb = gridDim.x - 1 - blockIdx.x;       // heavy blocks first
    int bh = blockIdx.y;
    int b = bh >> 4, h = bh & 15;
    int tid = threadIdx.x, lane = tid & 31, warp = tid >> 5;   // warp 0..3
    int tg = lane >> 2, ti = lane & 3;
    int q0 = qb * 128;
    int kmax = 2 * qb + 1;

    // ldmatrix per-lane addressing
    int t_ = lane >> 3, rr = lane & 7;
    uint32_t qoff[2];
    #pragma unroll
    for (int i = 0; i < 2; i++)
        qoff[i] = (uint32_t)(((warp * 32 + i * 16 + (t_ & 1) * 8 + rr) * AS
                              + (t_ >> 1) * 4) * 4);
    uint32_t kvoff = (uint32_t)((((t_ >> 1) * 8 + rr) * AS + (t_ & 1) * 4) * 4);

    // Q tile -> Qs: 128x64 floats, 2048 16B chunks / 128 threads
    {
        #pragma unroll
        for (int u = 0; u < 16; u++) {
            int i = tid + u * 128;
            int r = i >> 4, c4 = (i & 15) * 4;
            const float* src = g_qkv + (size_t)(b * Tsz + q0 + r) * 3072 + h * 64 + c4;
            CP_ASYNC16(smemB + (uint32_t)(r * AS + c4) * 4, src);
        }
    }

    auto load_kv = [&](int kb) {
        if (kb <= kmax) {
            uint32_t kB = smemB + (uint32_t)(128 * AS + (kb & 1) * 2 * 64 * AS) * 4;
            #pragma unroll
            for (int u = 0; u < 8; u++) {
                int i = tid + u * 128;
                int r = i >> 4, c4 = (i & 15) * 4;
                const float* kg = g_qkv + (size_t)(b * Tsz + kb * 64 + r) * 3072 + 1024 + h * 64 + c4;
                CP_ASYNC16(kB + (uint32_t)(r * AS + c4) * 4, kg);
                const float* vg = g_vT + ((size_t)bh * 64 + r) * Tsz + kb * 64 + c4;
                CP_ASYNC16(kB + (uint32_t)(64 * AS + r * AS + c4) * 4, vg);
            }
        }
        CP_COMMIT();
    };

    load_kv(0);   // Q rides in this group

    float o[2][8][4];
    #pragma unroll
    for (int i = 0; i < 2; i++)
        #pragma unroll
        for (int j = 0; j < 8; j++)
            #pragma unroll
            for (int q = 0; q < 4; q++) o[i][j][q] = 0.f;
    float mr[2][2] = {{-1e30f, -1e30f}, {-1e30f, -1e30f}};
    float lr[2][2] = {{0.f, 0.f}, {0.f, 0.f}};

    #pragma unroll 1
    for (int kb = 0; kb <= kmax; kb++) {
        CP_WAIT(0);
        __syncthreads();
        load_kv(kb + 1);

        uint32_t KsB = smemB + (uint32_t)(128 * AS + (kb & 1) * 2 * 64 * AS) * 4;
        uint32_t VtB = KsB + 64 * AS * 4;

        // ---- S = Q K^T ----
        float s[2][8][4];
        #pragma unroll
        for (int i = 0; i < 2; i++)
            #pragma unroll
            for (int j = 0; j < 8; j++)
                #pragma unroll
                for (int q = 0; q < 4; q++) s[i][j][q] = 0.f;

        #pragma unroll
        for (int kt = 0; kt < 8; kt++) {
            uint32_t af[2][4], bk[4][4];
            ldsm4(smemB + qoff[0] + kt * 32, af[0]);
            ldsm4(smemB + qoff[1] + kt * 32, af[1]);
            #pragma unroll
            for (int p = 0; p < 4; p++)
                ldsm4(KsB + kvoff + (uint32_t)(p * 16 * AS * 4) + kt * 32, bk[p]);
            #pragma unroll
            for (int i = 0; i < 2; i++)
                #pragma unroll
                for (int p = 0; p < 4; p++) {
                    MMA_TF32(s[i][2 * p],     af[i], &bk[p][0]);
                    MMA_TF32(s[i][2 * p + 1], af[i], &bk[p][2]);
                }
        }

        // ---- causal mask ----
        if (kb >= 2 * qb) {
            #pragma unroll
            for (int i = 0; i < 2; i++) {
                int row0 = q0 + warp * 32 + i * 16 + tg;
                #pragma unroll
                for (int j = 0; j < 8; j++) {
                    int col = kb * 64 + j * 8 + 2 * ti;
                    if (col     > row0    ) s[i][j][0] = -1e30f;
                    if (col + 1 > row0    ) s[i][j][1] = -1e30f;
                    if (col     > row0 + 8) s[i][j][2] = -1e30f;
                    if (col + 1 > row0 + 8) s[i][j][3] = -1e30f;
                }
            }
        }

        // ---- online softmax (exp2 domain), per row-group i ----
        float sc[2][2];
        #pragma unroll
        for (int i = 0; i < 2; i++) {
            float mt0 = -1e30f, mt1 = -1e30f;
            #pragma unroll
            for (int j = 0; j < 8; j++) {
                mt0 = fmaxf(mt0, fmaxf(s[i][j][0], s[i][j][1]));
                mt1 = fmaxf(mt1, fmaxf(s[i][j][2], s[i][j][3]));
            }
            mt0 = fmaxf(mt0, __shfl_xor_sync(0xffffffffu, mt0, 1));
            mt0 = fmaxf(mt0, __shfl_xor_sync(0xffffffffu, mt0, 2));
            mt1 = fmaxf(mt1, __shfl_xor_sync(0xffffffffu, mt1, 1));
            mt1 = fmaxf(mt1, __shfl_xor_sync(0xffffffffu, mt1, 2));

            float mn0 = fmaxf(mr[i][0], mt0), mn1 = fmaxf(mr[i][1], mt1);
            sc[i][0] = ex2(mr[i][0] - mn0); sc[i][1] = ex2(mr[i][1] - mn1);
            float ps0 = 0.f, ps1 = 0.f;
            #pragma unroll
            for (int j = 0; j < 8; j++) {
                s[i][j][0] = ex2(s[i][j][0] - mn0); ps0 += s[i][j][0];
                s[i][j][1] = ex2(s[i][j][1] - mn0); ps0 += s[i][j][1];
                s[i][j][2] = ex2(s[i][j][2] - mn1); ps1 += s[i][j][2];
                s[i][j][3] = ex2(s[i][j][3] - mn1); ps1 += s[i][j][3];
            }
            ps0 += __shfl_xor_sync(0xffffffffu, ps0, 1);
            ps0 += __shfl_xor_sync(0xffffffffu, ps0, 2);
            ps1 += __shfl_xor_sync(0xffffffffu, ps1, 1);
            ps1 += __shfl_xor_sync(0xffffffffu, ps1, 2);
            lr[i][0] = lr[i][0] * sc[i][0] + ps0; mr[i][0] = mn0;
            lr[i][1] = lr[i][1] * sc[i][1] + ps1; mr[i][1] = mn1;

            #pragma unroll
            for (int j = 0; j < 8; j++) {
                o[i][j][0] *= sc[i][0]; o[i][j][1] *= sc[i][0];
                o[i][j][2] *= sc[i][1]; o[i][j][3] *= sc[i][1];
                s[i][j][0] = to_tf32(s[i][j][0]); s[i][j][1] = to_tf32(s[i][j][1]);
                s[i][j][2] = to_tf32(s[i][j][2]); s[i][j][3] = to_tf32(s[i][j][3]);
            }
        }

        // ---- O += P V ----
        int src0 = (lane & ~3) | (ti >> 1);
        int src1 = src0 + 2;
        bool odd = (ti & 1) != 0;
        #pragma unroll
        for (int kt = 0; kt < 8; kt++) {
            uint32_t af[2][4], bv[4][4];
            #pragma unroll
            for (int i = 0; i < 2; i++) {
                float v00 = __shfl_sync(0xffffffffu, s[i][kt][0], src0);
                float v01 = __shfl_sync(0xffffffffu, s[i][kt][1], src0);
                float v02 = __shfl_sync(0xffffffffu, s[i][kt][2], src0);
                float v03 = __shfl_sync(0xffffffffu, s[i][kt][3], src0);
                float v10 = __shfl_sync(0xffffffffu, s[i][kt][0], src1);
                float v11 = __shfl_sync(0xffffffffu, s[i][kt][1], src1);
                float v12 = __shfl_sync(0xffffffffu, s[i][kt][2], src1);
                float v13 = __shfl_sync(0xffffffffu, s[i][kt][3], src1);
                af[i][0] = __float_as_uint(odd ? v01 : v00);
                af[i][1] = __float_as_uint(odd ? v03 : v02);
                af[i][2] = __float_as_uint(odd ? v11 : v10);
                af[i][3] = __float_as_uint(odd ? v13 : v12);
            }
            #pragma unroll
            for (int p = 0; p < 4; p++)
                ldsm4(VtB + kvoff + (uint32_t)(p * 16 * AS * 4) + kt * 32, bv[p]);
            #pragma unroll
            for (int i = 0; i < 2; i++)
                #pragma unroll
                for (int p = 0; p < 4; p++) {
                    MMA_TF32(o[i][2 * p],     af[i], &bv[p][0]);
                    MMA_TF32(o[i][2 * p + 1], af[i], &bv[p][2]);
                }
        }
    }

    // ---- epilogue ----
    #pragma unroll
    for (int i = 0; i < 2; i++) {
        float i0 = 1.f / lr[i][0], i1 = 1.f / lr[i][1];
        size_t m0 = (size_t)(b * Tsz + q0 + warp * 32 + i * 16 + tg);
        #pragma unroll
        for (int jd = 0; jd < 8; jd++) {
            int col = h * 64 + jd * 8 + 2 * ti;
            float2 w0 = make_float2(to_tf32(o[i][jd][0] * i0), to_tf32(o[i][jd][1] * i0));
            float2 w1 = make_float2(to_tf32(o[i][jd][2] * i1), to_tf32(o[i][jd][3] * i1));
            *(float2*)&g_y[m0 * 1024 + col] = w0;
            *(float2*)&g_y[(m0 + 8) * 1024 + col] = w1;
        }
    }
}

// ---------------------------------------------------------------------------
extern "C" void kernel_launch(void* const* d_in, const int* in_sizes, int n_in,
                              void* d_out, int out_size)
{
    const float* x      = (const float*)d_in[0];
    const float* w_qkv  = (const float*)d_in[1];
    const float* b_qkv  = (const float*)d_in[2];
    const float* w_proj = (const float*)d_in[3];
    const float* b_proj = (const float*)d_in[4];
    float* out = (float*)d_out;

    float* wqkvT; cudaGetSymbolAddress((void**)&wqkvT, g_wqkvT);
    float* wpT;   cudaGetSymbolAddress((void**)&wpT,   g_wpT);
    float* qkv;   cudaGetSymbolAddress((void**)&qkv,   g_qkv);
    float* y;     cudaGetSymbolAddress((void**)&y,     g_y);
    float* xc;    cudaGetSymbolAddress((void**)&xc,    g_xc);
    float* vT;    cudaGetSymbolAddress((void**)&vT,    g_vT);

    // 0) prep: tf32-round x; transpose+round weights
    {
        int n4 = Mrows * Csz / 4;
        cvt4_kernel<<<n4 / 256, 256>>>((const float4*)x, (float4*)xc, n4);
        dim3 g1(3 * Csz / 32, Csz / 32);
        transpose_cvt_kernel<<<g1, 256>>>(w_qkv, wqkvT, Csz, 3 * Csz);
        dim3 g2(Csz / 32, Csz / 32);
        transpose_cvt_kernel<<<g2, 256>>>(w_proj, wpT, Csz, Csz);
    }

    // 1) qkv = x @ w_qkv + b_qkv   (q pre-scaled, v scattered to vT, rounded)
    {
        cudaFuncSetAttribute(gemm_mma_kernel,
                             cudaFuncAttributeMaxDynamicSharedMemorySize, GEMM_SMEM);
        dim3 grid(3 * Csz / 128, Mrows / 128);
        gemm_mma_kernel<<<grid, 128, GEMM_SMEM>>>(xc, wqkvT, b_qkv, qkv, 3 * Csz, vT, 1);
    }

    // 2) tensor-core flash attention -> g_y
    {
        cudaFuncSetAttribute(attn_mma_kernel,
                             cudaFuncAttributeMaxDynamicSharedMemorySize, ATT_SMEM);
        dim3 grid(Tsz / 128, Bsz * Hn);
        attn_mma_kernel<<<grid, 128, ATT_SMEM>>>();
    }

    // 3) out = y @ w_proj + b_proj
    {
        dim3 grid(Csz / 128, Mrows / 128);
        gemm_mma_kernel<<<grid, 128, GEMM_SMEM>>>(y, wpT, b_proj, out, Csz, nullptr, 0);
    }
}

// round 10
// speedup vs baseline: 2.1620x; 1.8747x over previous
#include <cuda_runtime.h>
#include <cuda_fp16.h>
#include <cstdint>
#include <cstddef>

#define Bsz   4
#define Tsz   2048
#define Csz   1024
#define Hn    16
#define Mrows (Bsz * Tsz)   // 8192

// 0.125 * log2(e): folded into q so softmax runs in exp2 domain
#define QSCALE 0.18033688011112042f

// Scratch (fp16 operands everywhere; f32 accumulation in-kernel)
__device__ __half g_qkvh [(size_t)Mrows * 3 * Csz];  // [8192, 3072]
__device__ __half g_yh   [(size_t)Mrows * Csz];      // [8192, 1024]
__device__ __half g_xh   [(size_t)Mrows * Csz];      // x in fp16
__device__ __half g_wqkvTh[(size_t)3 * Csz * Csz];   // [3072, 1024]
__device__ __half g_wpTh [(size_t)Csz * Csz];        // [1024, 1024]

// ---------------------------------------------------------------------------
// Helpers (non-'a' PTX: cp.async + mma.sync + ldmatrix, sm_80 baseline)
// ---------------------------------------------------------------------------
__device__ __forceinline__ uint32_t smem_to_u32(const void* p) {
    uint32_t a;
    asm("{ .reg .u64 t; cvta.to.shared.u64 t, %1; cvt.u32.u64 %0, t; }"
        : "=r"(a) : "l"(p));
    return a;
}
__device__ __forceinline__ float ex2(float x) {
    float r;
    asm("ex2.approx.f32 %0, %1;" : "=f"(r) : "f"(x));
    return r;
}
__device__ __forceinline__ uint32_t packh2(float lo, float hi) {
    __half2 h = __floats2half2_rn(lo, hi);
    return *reinterpret_cast<uint32_t*>(&h);
}
__device__ __forceinline__ void ldsm4(uint32_t addr, uint32_t* r) {
    asm volatile("ldmatrix.sync.aligned.m8n8.x4.shared.b16 {%0,%1,%2,%3}, [%4];"
        : "=r"(r[0]), "=r"(r[1]), "=r"(r[2]), "=r"(r[3]) : "r"(addr));
}
__device__ __forceinline__ void ldsm4t(uint32_t addr, uint32_t* r) {
    asm volatile("ldmatrix.sync.aligned.m8n8.x4.trans.shared.b16 {%0,%1,%2,%3}, [%4];"
        : "=r"(r[0]), "=r"(r[1]), "=r"(r[2]), "=r"(r[3]) : "r"(addr));
}

#define CP_ASYNC16(dst, src) \
    asm volatile("cp.async.cg.shared.global [%0], [%1], 16;" :: "r"(dst), "l"(src) : "memory")
#define CP_COMMIT() asm volatile("cp.async.commit_group;" ::: "memory")
#define CP_WAIT(n)  asm volatile("cp.async.wait_group %0;" :: "n"(n) : "memory")

// D += A*B, m16n8k16 fp16 inputs, f32 accumulate (A row-major, B col-major)
#define MMA_F16(d, a, b) \
    asm volatile("mma.sync.aligned.m16n8k16.row.col.f32.f16.f16.f32 " \
        "{%0,%1,%2,%3}, {%4,%5,%6,%7}, {%8,%9}, {%0,%1,%2,%3};" \
        : "+f"((d)[0]), "+f"((d)[1]), "+f"((d)[2]), "+f"((d)[3]) \
        : "r"((a)[0]), "r"((a)[1]), "r"((a)[2]), "r"((a)[3]), \
          "r"((b)[0]), "r"((b)[1]))

// ---------------------------------------------------------------------------
// fp16 GEMM: C[M,N] = A[M,1024] @ Bt[N,1024]^T + bias
// 128x128 CTA tile, BK=64 (128B fp16 rows), 3-stage cp.async, 128 threads
// (2x2 warps, warp tile 64x64). qkvMode=1: store fp16 to g_qkvh (q cols
// pre-scaled by QSCALE); qkvMode=0: store f32 to Cf.
// ---------------------------------------------------------------------------
#define KCH 16
#define STAGE_B 32768
#define GEMM_SMEM (3 * STAGE_B)

__global__ __launch_bounds__(128, 2) void gemm_h_kernel(
    const __half* __restrict__ A,
    const __half* __restrict__ Bt,
    const float* __restrict__ bias,
    float* __restrict__ Cf,
    int Ntot,
    int qkvMode)
{
    extern __shared__ char smraw[];
    uint32_t smemB = smem_to_u32(smraw);

    int tid = threadIdx.x, lane = tid & 31, warp = tid >> 5;
    int wm = warp >> 1, wn = warp & 1;
    int tg = lane >> 2, ti = lane & 3;
    int t_ = lane >> 3, rr = lane & 7;
    int row0 = blockIdx.y * 128, col0 = blockIdx.x * 128;

    // cp.async mapping: rows of 128B (64 halves), 8 segs of 16B
    int ldr  = tid >> 3;               // 0..15
    int lseg = tid & 7;
    uint32_t lsw = ((uint32_t)(lseg ^ (ldr & 7))) << 4;
    const __half* gA = A  + (size_t)(row0 + ldr) * 1024 + lseg * 8;
    const __half* gB = Bt + (size_t)(col0 + ldr) * 1024 + lseg * 8;

    // ldmatrix row bases (byte offsets; all rows ≡ rr mod 8)
    uint32_t arow[4], brow[4];
    #pragma unroll
    for (int i = 0; i < 4; i++)
        arow[i] = (uint32_t)((wm * 64 + i * 16 + (t_ & 1) * 8 + rr) * 128);
    #pragma unroll
    for (int p = 0; p < 4; p++)
        brow[p] = (uint32_t)((wn * 64 + p * 16 + (t_ >> 1) * 8 + rr) * 128);

    float acc[4][8][4];
    #pragma unroll
    for (int i = 0; i < 4; i++)
        #pragma unroll
        for (int j = 0; j < 8; j++)
            #pragma unroll
            for (int q = 0; q < 4; q++) acc[i][j][q] = 0.f;

    auto load_stage = [&](int c) {
        if (c < KCH) {
            uint32_t base = smemB + (uint32_t)(c % 3) * STAGE_B;
            #pragma unroll
            for (int j = 0; j < 8; j++) {
                uint32_t off = (uint32_t)((ldr + 16 * j) * 128) + lsw;
                CP_ASYNC16(base + off, gA + c * 64 + (size_t)j * 16 * 1024);
                CP_ASYNC16(base + 16384 + off, gB + c * 64 + (size_t)j * 16 * 1024);
            }
        }
        CP_COMMIT();
    };

    load_stage(0);
    load_stage(1);

    #pragma unroll 1
    for (int c = 0; c < KCH; ++c) {
        CP_WAIT(1);
        __syncthreads();
        load_stage(c + 2);

        uint32_t AsB = smemB + (uint32_t)(c % 3) * STAGE_B;
        uint32_t BsB = AsB + 16384;

        #pragma unroll
        for (int ks = 0; ks < 4; ks++) {
            uint32_t af[4][4], bf[4][4];
            #pragma unroll
            for (int i = 0; i < 4; i++)
                ldsm4(AsB + arow[i] + ((uint32_t)((ks * 2 + (t_ >> 1)) ^ rr) << 4), af[i]);
            #pragma unroll
            for (int p = 0; p < 4; p++)
                ldsm4(BsB + brow[p] + ((uint32_t)((ks * 2 + (t_ & 1)) ^ rr) << 4), bf[p]);
            #pragma unroll
            for (int i = 0; i < 4; i++)
                #pragma unroll
                for (int p = 0; p < 4; p++) {
                    MMA_F16(acc[i][2 * p],     af[i], &bf[p][0]);
                    MMA_F16(acc[i][2 * p + 1], af[i], &bf[p][2]);
                }
        }
    }

    if (qkvMode) {
        float osc = (col0 < 1024) ? QSCALE : 1.0f;   // q third pre-scale
        #pragma unroll
        for (int i = 0; i < 4; i++) {
            int m = row0 + wm * 64 + i * 16 + tg;
            #pragma unroll
            for (int j = 0; j < 8; j++) {
                int n = col0 + wn * 64 + j * 8 + 2 * ti;
                float bx = __ldg(bias + n), by = __ldg(bias + n + 1);
                uint32_t h0 = packh2((acc[i][j][0] + bx) * osc, (acc[i][j][1] + by) * osc);
                uint32_t h1 = packh2((acc[i][j][2] + bx) * osc, (acc[i][j][3] + by) * osc);
                *(uint32_t*)&g_qkvh[(size_t)m * 3072 + n] = h0;
                *(uint32_t*)&g_qkvh[(size_t)(m + 8) * 3072 + n] = h1;
            }
        }
    } else {
        #pragma unroll
        for (int i = 0; i < 4; i++) {
            int m = row0 + wm * 64 + i * 16 + tg;
            #pragma unroll
            for (int j = 0; j < 8; j++) {
                int n = col0 + wn * 64 + j * 8 + 2 * ti;
                float bx = __ldg(bias + n), by = __ldg(bias + n + 1);
                *(float2*)&Cf[(size_t)m * Ntot + n] =
                    make_float2(acc[i][j][0] + bx, acc[i][j][1] + by);
                *(float2*)&Cf[(size_t)(m + 8) * Ntot + n] =
                    make_float2(acc[i][j][2] + bx, acc[i][j][3] + by);
            }
        }
    }
}

// ---------------------------------------------------------------------------
// prep kernels: f32 -> fp16 (and transpose for weights)
// ---------------------------------------------------------------------------
__global__ __launch_bounds__(256) void cvth_kernel(
    const float4* __restrict__ in, __half2* __restrict__ out, int n4)
{
    int i = blockIdx.x * 256 + threadIdx.x;
    if (i < n4) {
        float4 v = in[i];
        out[2 * i]     = __floats2half2_rn(v.x, v.y);
        out[2 * i + 1] = __floats2half2_rn(v.z, v.w);
    }
}

__global__ __launch_bounds__(256) void transpose_cvth_kernel(
    const float* __restrict__ in, __half* __restrict__ out, int R, int C)
{
    __shared__ float t[32][33];
    int c0 = blockIdx.x * 32, r0 = blockIdx.y * 32;
    int tx = threadIdx.x & 31, ty = threadIdx.x >> 5;
    #pragma unroll
    for (int i = ty; i < 32; i += 8)
        t[i][tx] = in[(size_t)(r0 + i) * C + c0 + tx];
    __syncthreads();
    #pragma unroll
    for (int i = ty; i < 32; i += 8)
        out[(size_t)(c0 + i) * R + r0 + tx] = __float2half_rn(t[tx][i]);
}

// ---------------------------------------------------------------------------
// fp16 tensor-core flash attention.
// Grid (16, 64). 128 threads, 4 warps, warp tile m32 x n64.
// Smem: Q[128][64h] + 2 stages of { K[64][64h], V[64][64h] } = 48 KB.
// S = QK^T via m16n8k16; P packed fp16 straight from the S accumulator
// (no shuffles); PV reads V via ldmatrix.trans (V stored naturally [t][d]).
// ---------------------------------------------------------------------------
#define ATT_SMEM 49152

__global__ __launch_bounds__(128, 2) void attn_h_kernel()
{
    extern __shared__ char smraw[];
    uint32_t smemB = smem_to_u32(smraw);

    int qb = gridDim.x - 1 - blockIdx.x;       // heavy blocks first
    int bh = blockIdx.y;
    int b = bh >> 4, h = bh & 15;
    int tid = threadIdx.x, lane = tid & 31, warp = tid >> 5;
    int tg = lane >> 2, ti = lane & 3;
    int t_ = lane >> 3, rr = lane & 7;
    int q0 = qb * 128;
    int kmax = 2 * qb + 1;

    int ldr  = tid >> 3;               // 0..15
    int lseg = tid & 7;
    uint32_t lsw = ((uint32_t)(lseg ^ (ldr & 7))) << 4;

    // Q tile (128 rows x 128B), committed with load_kv(0)
    #pragma unroll
    for (int u = 0; u < 8; u++) {
        int row = ldr + 16 * u;
        const __half* src = g_qkvh + (size_t)(b * Tsz + q0 + row) * 3072 + h * 64 + lseg * 8;
        CP_ASYNC16(smemB + (uint32_t)(row * 128) + lsw, src);
    }

    auto load_kv = [&](int kb) {
        if (kb <= kmax) {
            uint32_t kB = smemB + 16384 + (uint32_t)(kb & 1) * 16384;
            #pragma unroll
            for (int u = 0; u < 4; u++) {
                int row = ldr + 16 * u;
                size_t g = (size_t)(b * Tsz + kb * 64 + row) * 3072 + h * 64 + lseg * 8;
                CP_ASYNC16(kB + (uint32_t)(row * 128) + lsw, g_qkvh + g + 1024);
                CP_ASYNC16(kB + 8192 + (uint32_t)(row * 128) + lsw, g_qkvh + g + 2048);
            }
        }
        CP_COMMIT();
    };

    load_kv(0);

    // ldmatrix row bases
    uint32_t qrow[2], krow[4];
    #pragma unroll
    for (int i = 0; i < 2; i++)
        qrow[i] = (uint32_t)((warp * 32 + i * 16 + (t_ & 1) * 8 + rr) * 128);
    #pragma unroll
    for (int p = 0; p < 4; p++)
        krow[p] = (uint32_t)((p * 16 + (t_ >> 1) * 8 + rr) * 128);

    float o[2][8][4];
    #pragma unroll
    for (int i = 0; i < 2; i++)
        #pragma unroll
        for (int j = 0; j < 8; j++)
            #pragma unroll
            for (int q = 0; q < 4; q++) o[i][j][q] = 0.f;
    float mrow[2][2] = {{-1e30f, -1e30f}, {-1e30f, -1e30f}};
    float lsum[2][2] = {{0.f, 0.f}, {0.f, 0.f}};

    #pragma unroll 1
    for (int kb = 0; kb <= kmax; kb++) {
        CP_WAIT(0);
        __syncthreads();
        load_kv(kb + 1);

        uint32_t KsB = smemB + 16384 + (uint32_t)(kb & 1) * 16384;
        uint32_t VsB = KsB + 8192;

        // ---- S = Q K^T ----
        float s[2][8][4];
        #pragma unroll
        for (int i = 0; i < 2; i++)
            #pragma unroll
            for (int j = 0; j < 8; j++)
                #pragma unroll
                for (int q = 0; q < 4; q++) s[i][j][q] = 0.f;

        #pragma unroll
        for (int kt = 0; kt < 4; kt++) {
            uint32_t af[2][4], bk[4][4];
            ldsm4(smemB + qrow[0] + ((uint32_t)((kt * 2 + (t_ >> 1)) ^ rr) << 4), af[0]);
            ldsm4(smemB + qrow[1] + ((uint32_t)((kt * 2 + (t_ >> 1)) ^ rr) << 4), af[1]);
            #pragma unroll
            for (int p = 0; p < 4; p++)
                ldsm4(KsB + krow[p] + ((uint32_t)((kt * 2 + (t_ & 1)) ^ rr) << 4), bk[p]);
            #pragma unroll
            for (int i = 0; i < 2; i++)
                #pragma unroll
                for (int p = 0; p < 4; p++) {
                    MMA_F16(s[i][2 * p],     af[i], &bk[p][0]);
                    MMA_F16(s[i][2 * p + 1], af[i], &bk[p][2]);
                }
        }

        // ---- causal mask ----
        if (kb >= 2 * qb) {
            #pragma unroll
            for (int i = 0; i < 2; i++) {
                int row0 = q0 + warp * 32 + i * 16 + tg;
                #pragma unroll
                for (int j = 0; j < 8; j++) {
                    int col = kb * 64 + j * 8 + 2 * ti;
                    if (col     > row0    ) s[i][j][0] = -1e30f;
                    if (col + 1 > row0    ) s[i][j][1] = -1e30f;
                    if (col     > row0 + 8) s[i][j][2] = -1e30f;
                    if (col + 1 > row0 + 8) s[i][j][3] = -1e30f;
                }
            }
        }

        // ---- online softmax (exp2 domain; Q pre-scaled) ----
        float sc[2][2];
        #pragma unroll
        for (int i = 0; i < 2; i++) {
            float mt0 = -1e30f, mt1 = -1e30f;
            #pragma unroll
            for (int j = 0; j < 8; j++) {
                mt0 = fmaxf(mt0, fmaxf(s[i][j][0], s[i][j][1]));
                mt1 = fmaxf(mt1, fmaxf(s[i][j][2], s[i][j][3]));
            }
            mt0 = fmaxf(mt0, __shfl_xor_sync(0xffffffffu, mt0, 1));
            mt0 = fmaxf(mt0, __shfl_xor_sync(0xffffffffu, mt0, 2));
            mt1 = fmaxf(mt1, __shfl_xor_sync(0xffffffffu, mt1, 1));
            mt1 = fmaxf(mt1, __shfl_xor_sync(0xffffffffu, mt1, 2));

            float mn0 = fmaxf(mrow[i][0], mt0), mn1 = fmaxf(mrow[i][1], mt1);
            sc[i][0] = ex2(mrow[i][0] - mn0); sc[i][1] = ex2(mrow[i][1] - mn1);
            float ps0 = 0.f, ps1 = 0.f;
            #pragma unroll
            for (int j = 0; j < 8; j++) {
                s[i][j][0] = ex2(s[i][j][0] - mn0); ps0 += s[i][j][0];
                s[i][j][1] = ex2(s[i][j][1] - mn0); ps0 += s[i][j][1];
                s[i][j][2] = ex2(s[i][j][2] - mn1); ps1 += s[i][j][2];
                s[i][j][3] = ex2(s[i][j][3] - mn1); ps1 += s[i][j][3];
            }
            ps0 += __shfl_xor_sync(0xffffffffu, ps0, 1);
            ps0 += __shfl_xor_sync(0xffffffffu, ps0, 2);
            ps1 += __shfl_xor_sync(0xffffffffu, ps1, 1);
            ps1 += __shfl_xor_sync(0xffffffffu, ps1, 2);
            lsum[i][0] = lsum[i][0] * sc[i][0] + ps0; mrow[i][0] = mn0;
            lsum[i][1] = lsum[i][1] * sc[i][1] + ps1; mrow[i][1] = mn1;

            #pragma unroll
            for (int j = 0; j < 8; j++) {
                o[i][j][0] *= sc[i][0]; o[i][j][1] *= sc[i][0];
                o[i][j][2] *= sc[i][1]; o[i][j][3] *= sc[i][1];
            }
        }

        // ---- O += P V : P fp16-packed straight from S acc (no shuffle) ----
        #pragma unroll
        for (int kt = 0; kt < 4; kt++) {
            uint32_t bv[4][4], af[2][4];
            #pragma unroll
            for (int p = 0; p < 4; p++)
                ldsm4t(VsB + (uint32_t)((kt * 16 + (t_ & 1) * 8 + rr) * 128)
                           + ((uint32_t)((p * 2 + (t_ >> 1)) ^ rr) << 4), bv[p]);
            #pragma unroll
            for (int i = 0; i < 2; i++) {
                af[i][0] = packh2(s[i][2 * kt][0],     s[i][2 * kt][1]);
                af[i][1] = packh2(s[i][2 * kt][2],     s[i][2 * kt][3]);
                af[i][2] = packh2(s[i][2 * kt + 1][0], s[i][2 * kt + 1][1]);
                af[i][3] = packh2(s[i][2 * kt + 1][2], s[i][2 * kt + 1][3]);
            }
            #pragma unroll
            for (int i = 0; i < 2; i++)
                #pragma unroll
                for (int p = 0; p < 4; p++) {
                    MMA_F16(o[i][2 * p],     af[i], &bv[p][0]);
                    MMA_F16(o[i][2 * p + 1], af[i], &bv[p][2]);
                }
        }
    }

    // ---- epilogue: normalize, fp16, store y ----
    #pragma unroll
    for (int i = 0; i < 2; i++) {
        float i0 = 1.f / lsum[i][0], i1 = 1.f / lsum[i][1];
        size_t m0 = (size_t)(b * Tsz + q0 + warp * 32 + i * 16 + tg);
        #pragma unroll
        for (int jd = 0; jd < 8; jd++) {
            int col = h * 64 + jd * 8 + 2 * ti;
            *(uint32_t*)&g_yh[m0 * 1024 + col] =
                packh2(o[i][jd][0] * i0, o[i][jd][1] * i0);
            *(uint32_t*)&g_yh[(m0 + 8) * 1024 + col] =
                packh2(o[i][jd][2] * i1, o[i][jd][3] * i1);
        }
    }
}

// ---------------------------------------------------------------------------
extern "C" void kernel_launch(void* const* d_in, const int* in_sizes, int n_in,
                              void* d_out, int out_size)
{
    const float* x      = (const float*)d_in[0];
    const float* w_qkv  = (const float*)d_in[1];
    const float* b_qkv  = (const float*)d_in[2];
    const float* w_proj = (const float*)d_in[3];
    const float* b_proj = (const float*)d_in[4];
    float* out = (float*)d_out;

    __half* xh;     cudaGetSymbolAddress((void**)&xh,     g_xh);
    __half* wqkvTh; cudaGetSymbolAddress((void**)&wqkvTh, g_wqkvTh);
    __half* wpTh;   cudaGetSymbolAddress((void**)&wpTh,   g_wpTh);
    __half* yh;     cudaGetSymbolAddress((void**)&yh,     g_yh);

    // 0) prep: fp16-convert x; transpose+convert weights
    {
        int n4 = Mrows * Csz / 4;
        cvth_kernel<<<n4 / 256, 256>>>((const float4*)x, (__half2*)xh, n4);
        dim3 g1(3 * Csz / 32, Csz / 32);
        transpose_cvth_kernel<<<g1, 256>>>(w_qkv, wqkvTh, Csz, 3 * Csz);
        dim3 g2(Csz / 32, Csz / 32);
        transpose_cvth_kernel<<<g2, 256>>>(w_proj, wpTh, Csz, Csz);
    }

    // 1) qkv = x @ w_qkv + b_qkv  -> g_qkvh fp16 (q pre-scaled)
    {
        cudaFuncSetAttribute(gemm_h_kernel,
                             cudaFuncAttributeMaxDynamicSharedMemorySize, GEMM_SMEM);
        dim3 grid(3 * Csz / 128, Mrows / 128);
        gemm_h_kernel<<<grid, 128, GEMM_SMEM>>>(xh, wqkvTh, b_qkv, nullptr, 3 * Csz, 1);
    }

    // 2) fp16 flash attention -> g_yh
    {
        cudaFuncSetAttribute(attn_h_kernel,
                             cudaFuncAttributeMaxDynamicSharedMemorySize, ATT_SMEM);
        dim3 grid(Tsz / 128, Bsz * Hn);
        attn_h_kernel<<<grid, 128, ATT_SMEM>>>();
    }

    // 3) out = y @ w_proj + b_proj  (f32 output)
    {
        dim3 grid(Csz / 128, Mrows / 128);
        gemm_h_kernel<<<grid, 128, GEMM_SMEM>>>(yh, wpTh, b_proj, out, Csz, 0);
    }
}